// round 1
// baseline (speedup 1.0000x reference)
#include <cuda_runtime.h>
#include <cstdint>

#define BHN 64            // B*H
#define NROWS 8192
#define DD 64
#define OUT_G_SIZE (BHN*NROWS*DD)        // 33554432
#define KV_OFF     OUT_G_SIZE
#define KV_SIZE    (BHN*DD*DD)           // 262144
#define NORM_OFF   (KV_OFF + KV_SIZE)
#define NORM_SIZE  (BHN*DD)              // 4096
#define EPSV 1e-10f
#define SMEM_FLOATS (4096 + 8192 + 8192 + 64 + 128)
#define SMEM_BYTES (SMEM_FLOATS * 4)

typedef unsigned long long ull;

__device__ __forceinline__ ull pk(float lo, float hi){
    ull r; asm("mov.b64 %0,{%1,%2};" : "=l"(r) : "f"(lo), "f"(hi)); return r;
}
__device__ __forceinline__ void upk(ull v, float& lo, float& hi){
    asm("mov.b64 {%0,%1},%2;" : "=f"(lo), "=f"(hi) : "l"(v));
}
__device__ __forceinline__ ull ffma2(ull a, ull b, ull c){
    ull d; asm("fma.rn.f32x2 %0,%1,%2,%3;" : "=l"(d) : "l"(a), "l"(b), "l"(c)); return d;
}
// XOR swizzle: keeps float4 groups contiguous (mask only touches bits 2..4),
// spreads rows-8-apart across banks for the GEMM1 column-broadcast reads.
__device__ __forceinline__ int swz(int n, int c){
    return (n << 6) + (c ^ (((n >> 3) & 7) << 2));
}
__device__ __forceinline__ float elu1(float x){
    return x > 0.f ? x + 1.f : __expf(x);
}

// Stage a 128x64 fp32 tile from gmem with elu(x)+1 applied, into swizzled smem.
__device__ __forceinline__ void stage_elu(const float* __restrict__ gsrc,
                                          float* __restrict__ sdst, int tid){
#pragma unroll
    for (int i = 0; i < 16; i++){
        int f = tid + (i << 7);
        int n = f >> 4, c4 = (f & 15) << 2;
        float4 v = *(const float4*)&gsrc[(size_t)n * 64 + c4];
        v.x = elu1(v.x); v.y = elu1(v.y); v.z = elu1(v.z); v.w = elu1(v.w);
        *(float4*)&sdst[swz(n, c4)] = v;
    }
}

// C[128x64] = sA[128x64] @ sKV[64x64], each thread owns an 8x8 tile as 8x4 f32x2.
// tj==0 lanes also fuse the denominator dot (sA row . sNorm) and publish 1/max(den,eps).
__device__ __forceinline__ void gemm_qk(const float* __restrict__ sA,
                                        const float* __restrict__ sKV,
                                        const float* __restrict__ sNorm,
                                        float* __restrict__ sInv,
                                        ull (&t2)[8][4], int ti, int tj, int amask){
    float denr[8] = {0.f,0.f,0.f,0.f,0.f,0.f,0.f,0.f};
#pragma unroll
    for (int r = 0; r < 8; r++){
        t2[r][0] = 0ull; t2[r][1] = 0ull; t2[r][2] = 0ull; t2[r][3] = 0ull;
    }
#pragma unroll 4
    for (int d = 0; d < 64; ++d){
        const float4 b0 = *(const float4*)&sKV[(d << 6) + 8*tj];
        const float4 b1 = *(const float4*)&sKV[(d << 6) + 8*tj + 4];
        const ull bb0 = pk(b0.x, b0.y), bb1 = pk(b0.z, b0.w);
        const ull bb2 = pk(b1.x, b1.y), bb3 = pk(b1.z, b1.w);
        const int dx = d ^ amask;
        const float nd = sNorm[d];
#pragma unroll
        for (int r = 0; r < 8; r++){
            const float a = sA[((8*ti + r) << 6) + dx];
            const ull a2 = pk(a, a);
            t2[r][0] = ffma2(a2, bb0, t2[r][0]);
            t2[r][1] = ffma2(a2, bb1, t2[r][1]);
            t2[r][2] = ffma2(a2, bb2, t2[r][2]);
            t2[r][3] = ffma2(a2, bb3, t2[r][3]);
            if (tj == 0) denr[r] = fmaf(a, nd, denr[r]);
        }
    }
    if (tj == 0){
#pragma unroll
        for (int r = 0; r < 8; r++)
            sInv[8*ti + r] = 1.0f / fmaxf(denr[r], EPSV);
    }
}

__global__ void init_tail(const float* __restrict__ pkv,
                          const float* __restrict__ pnorm,
                          float* __restrict__ dout){
    int i = blockIdx.x * 256 + threadIdx.x;
    if (i < KV_SIZE)   dout[KV_OFF + i]   = pkv[i];
    if (i < NORM_SIZE) dout[NORM_OFF + i] = pnorm[i];
}

__global__ void __launch_bounds__(128, 2) fw_kernel(
    const float* __restrict__ keys, const float* __restrict__ values,
    const float* __restrict__ queries, const float* __restrict__ outin,
    const float* __restrict__ pkv, const float* __restrict__ pnorm,
    const float* __restrict__ gates, float* __restrict__ dout)
{
    extern __shared__ float sm[];
    float* sKV   = sm;            // 64x64
    float* sK    = sm + 4096;     // 128x64 swizzled (keys -> queries reuse)
    float* sV    = sm + 12288;    // 128x64 swizzled
    float* sNorm = sm + 20480;    // 64
    float* sInv  = sm + 20544;    // 128

    const int tid = threadIdx.x;
    const int bh  = blockIdx.y;
    const int ti  = tid >> 3;     // 0..15
    const int tj  = tid & 7;      // 0..7
    const int amask = (ti & 7) << 2;
    const size_t gOff = (size_t)bh * (NROWS * 64);

    {   // cache past_kv + past_norm for this (b,h)
        const float4* g4 = (const float4*)(pkv + (size_t)bh * 4096);
        float4* s4 = (float4*)sKV;
#pragma unroll
        for (int i = 0; i < 8; i++) s4[tid + i*128] = g4[tid + i*128];
        if (tid < 64) sNorm[tid] = pnorm[bh*64 + tid];
    }
    // gate and (1-gate) both computed at full precision
    const float et  = __expf(-gates[bh & 15]);
    const float gte = 1.f / (1.f + et);
    const float omg = et / (1.f + et);

    ull acc2[4][4];               // persistent k^T v partial: d = 4*ti+dr, e-pairs 8*tj+2p
#pragma unroll
    for (int a = 0; a < 4; a++)
#pragma unroll
        for (int b = 0; b < 4; b++) acc2[a][b] = 0ull;
    float nrm[4] = {0.f, 0.f, 0.f, 0.f};

    __syncthreads();

    const int rowStart = blockIdx.x * 256;

    for (int ch = 0; ch < 2; ++ch){
        const int row0 = rowStart + ch * 128;

        // ---- stage k = elu(keys)+1 ----
        stage_elu(keys + gOff + (size_t)row0 * 64, sK, tid);
        __syncthreads();

        // ---- GEMM1: tmp = k @ past_kv ; denom fused ----
        ull t2[8][4];
        gemm_qk(sK, sKV, sNorm, sInv, t2, ti, tj, amask);
        __syncthreads();

        // ---- v = values - tmp * inv_den -> sV ----
#pragma unroll
        for (int r = 0; r < 8; r++){
            const int n = 8*ti + r;
            const float inv = sInv[n];
            const float* gv = &values[gOff + (size_t)(row0 + n) * 64 + 8*tj];
            float4 va = *(const float4*)gv;
            float4 vb = *(const float4*)(gv + 4);
            float m0,m1,m2,m3,m4,m5,m6,m7;
            upk(t2[r][0], m0, m1); upk(t2[r][1], m2, m3);
            upk(t2[r][2], m4, m5); upk(t2[r][3], m6, m7);
            va.x -= m0*inv; va.y -= m1*inv; va.z -= m2*inv; va.w -= m3*inv;
            vb.x -= m4*inv; vb.y -= m5*inv; vb.z -= m6*inv; vb.w -= m7*inv;
            *(float4*)&sV[swz(n, 8*tj)]     = va;
            *(float4*)&sV[swz(n, 8*tj + 4)] = vb;
        }
        __syncthreads();

        // ---- GEMM2: acc += k^T v ; new_norm column sums fused on tj==0 ----
#pragma unroll 4
        for (int n = 0; n < 128; ++n){
            const float4 a  = *(const float4*)&sK[swz(n, 4*ti)];
            const float4 v0 = *(const float4*)&sV[swz(n, 8*tj)];
            const float4 v1 = *(const float4*)&sV[swz(n, 8*tj + 4)];
            const ull b0 = pk(v0.x, v0.y), b1 = pk(v0.z, v0.w);
            const ull b2 = pk(v1.x, v1.y), b3 = pk(v1.z, v1.w);
            const ull a0 = pk(a.x, a.x), a1 = pk(a.y, a.y);
            const ull a2 = pk(a.z, a.z), a3 = pk(a.w, a.w);
            acc2[0][0] = ffma2(a0, b0, acc2[0][0]);
            acc2[0][1] = ffma2(a0, b1, acc2[0][1]);
            acc2[0][2] = ffma2(a0, b2, acc2[0][2]);
            acc2[0][3] = ffma2(a0, b3, acc2[0][3]);
            acc2[1][0] = ffma2(a1, b0, acc2[1][0]);
            acc2[1][1] = ffma2(a1, b1, acc2[1][1]);
            acc2[1][2] = ffma2(a1, b2, acc2[1][2]);
            acc2[1][3] = ffma2(a1, b3, acc2[1][3]);
            acc2[2][0] = ffma2(a2, b0, acc2[2][0]);
            acc2[2][1] = ffma2(a2, b1, acc2[2][1]);
            acc2[2][2] = ffma2(a2, b2, acc2[2][2]);
            acc2[2][3] = ffma2(a2, b3, acc2[2][3]);
            acc2[3][0] = ffma2(a3, b0, acc2[3][0]);
            acc2[3][1] = ffma2(a3, b1, acc2[3][1]);
            acc2[3][2] = ffma2(a3, b2, acc2[3][2]);
            acc2[3][3] = ffma2(a3, b3, acc2[3][3]);
            if (tj == 0){ nrm[0] += a.x; nrm[1] += a.y; nrm[2] += a.z; nrm[3] += a.w; }
        }
        __syncthreads();

        // ---- stage q = elu(queries)+1 (reuse sK) ----
        stage_elu(queries + gOff + (size_t)row0 * 64, sK, tid);
        __syncthreads();

        // ---- GEMM3: mem = q @ past_kv ; denom_q fused ----
        gemm_qk(sK, sKV, sNorm, sInv, t2, ti, tj, amask);
        __syncthreads();

        // ---- epilogue: out_g = out * g + mem * inv_den * (1-g) ----
#pragma unroll
        for (int r = 0; r < 8; r++){
            const int n = 8*ti + r;
            const float s = sInv[n] * omg;
            const float* go = &outin[gOff + (size_t)(row0 + n) * 64 + 8*tj];
            float4 oa = *(const float4*)go;
            float4 ob = *(const float4*)(go + 4);
            float m0,m1,m2,m3,m4,m5,m6,m7;
            upk(t2[r][0], m0, m1); upk(t2[r][1], m2, m3);
            upk(t2[r][2], m4, m5); upk(t2[r][3], m6, m7);
            oa.x = oa.x*gte + m0*s; oa.y = oa.y*gte + m1*s;
            oa.z = oa.z*gte + m2*s; oa.w = oa.w*gte + m3*s;
            ob.x = ob.x*gte + m4*s; ob.y = ob.y*gte + m5*s;
            ob.z = ob.z*gte + m6*s; ob.w = ob.w*gte + m7*s;
            float* po = &dout[gOff + (size_t)(row0 + n) * 64 + 8*tj];
            *(float4*)po       = oa;
            *(float4*)(po + 4) = ob;
        }
        // no sync needed: next chunk's smem writes are fenced by the
        // post-staging __syncthreads before anyone re-reads/overwrites sInv.
    }

    // ---- flush block-partial new_kv / new_norm ----
    float* kvout = dout + KV_OFF + bh * 4096;
#pragma unroll
    for (int dr = 0; dr < 4; dr++){
        const int d = 4*ti + dr;
#pragma unroll
        for (int p = 0; p < 4; p++){
            float lo, hi; upk(acc2[dr][p], lo, hi);
            atomicAdd(&kvout[d*64 + 8*tj + 2*p],     lo);
            atomicAdd(&kvout[d*64 + 8*tj + 2*p + 1], hi);
        }
    }
    if (tj == 0){
        float* no = dout + NORM_OFF + bh*64 + 4*ti;
#pragma unroll
        for (int dr = 0; dr < 4; dr++) atomicAdd(&no[dr], nrm[dr]);
    }
}

extern "C" void kernel_launch(void* const* d_in, const int* in_sizes, int n_in,
                              void* d_out, int out_size)
{
    const float* keys    = (const float*)d_in[0];
    const float* values  = (const float*)d_in[1];
    const float* queries = (const float*)d_in[2];
    const float* outin   = (const float*)d_in[3];
    const float* pkv     = (const float*)d_in[4];
    const float* pnorm   = (const float*)d_in[5];
    const float* gates   = (const float*)d_in[6];
    float* dout = (float*)d_out;

    // >48KB dynamic smem opt-in (persists from the uncaptured correctness call).
    cudaFuncSetAttribute(fw_kernel, cudaFuncAttributeMaxDynamicSharedMemorySize, SMEM_BYTES);

    init_tail<<<1024, 256>>>(pkv, pnorm, dout);
    fw_kernel<<<dim3(32, 64), 128, SMEM_BYTES>>>(keys, values, queries, outin,
                                                 pkv, pnorm, gates, dout);
}

// round 2
// speedup vs baseline: 1.2393x; 1.2393x over previous
#include <cuda_runtime.h>
#include <cstdint>

#define KV_OFF   (64*8192*64)
#define KV_SIZE  (64*64*64)
#define NORM_OFF (KV_OFF + KV_SIZE)
#define NORM_SIZE (64*64)
#define EPSV 1e-10f

// smem float offsets
#define S_A  4096      // 128x64 k/q tile (swizzled)
#define S_B  12288     // 128x64 values->v / q tile (swizzled)
#define S_N  20480     // 64 past_norm
#define S_I  20544     // 128 reciprocal denominators
#define SMEM_FLOATS 20672
#define SMEM_BYTES (SMEM_FLOATS*4)

typedef unsigned long long ull;

__device__ __forceinline__ ull pk(float lo, float hi){
    ull r; asm("mov.b64 %0,{%1,%2};" : "=l"(r) : "f"(lo), "f"(hi)); return r;
}
__device__ __forceinline__ void upk(ull v, float& lo, float& hi){
    asm("mov.b64 {%0,%1},%2;" : "=f"(lo), "=f"(hi) : "l"(v));
}
__device__ __forceinline__ ull ffma2(ull a, ull b, ull c){
    ull d; asm("fma.rn.f32x2 %0,%1,%2,%3;" : "=l"(d) : "l"(a), "l"(b), "l"(c)); return d;
}
// 4-row-granular XOR swizzle: rows 4 apart get distinct bank shifts; float4 alignment kept.
__device__ __forceinline__ int swz4(int n, int c){
    return (n << 6) + (c ^ (((n >> 2) & 7) << 2));
}
__device__ __forceinline__ float elu1(float x){ return x > 0.f ? x + 1.f : __expf(x); }

__device__ __forceinline__ uint32_t s2u(const void* p){
    return (uint32_t)__cvta_generic_to_shared(p);
}
__device__ __forceinline__ void cpa16(uint32_t s, const void* g){
    asm volatile("cp.async.cg.shared.global [%0], [%1], 16;" :: "r"(s), "l"(g));
}
#define CP_COMMIT() asm volatile("cp.async.commit_group;")
#define CP_WAIT(n)  asm volatile("cp.async.wait_group %0;" :: "n"(n))

// async-copy one 128x64 fp32 tile gmem -> swizzled smem (8 x 16B per thread, coalesced)
__device__ __forceinline__ void cp_tile(const float* __restrict__ g,
                                        float* __restrict__ s, int tid){
#pragma unroll
    for (int i = 0; i < 8; i++){
        int f = tid + (i << 8);
        int n = f >> 4, c4 = (f & 15) << 2;
        cpa16(s2u(&s[swz4(n, c4)]), &g[(n << 6) + c4]);
    }
}

// C[128x64] = sA @ sKV; thread tile 4 rows x cols {4tj..+3, 4tj+32..+35} as 4x4 f32x2.
// tj==0 lanes fuse the denominator dot (row . norm) and publish reciprocals to sI.
__device__ __forceinline__ void gemm_qk(const float* __restrict__ sA,
                                        const float* __restrict__ sKV,
                                        const float* __restrict__ sN,
                                        float* __restrict__ sI,
                                        ull (&t2)[4][4], int ti, int tj){
    const int amask = (ti & 7) << 2;
    const int rb0 = (4*ti) << 6, rb1 = rb0 + 64, rb2 = rb0 + 128, rb3 = rb0 + 192;
    float den0 = 0.f, den1 = 0.f, den2 = 0.f, den3 = 0.f;
#pragma unroll
    for (int r = 0; r < 4; r++){ t2[r][0]=0; t2[r][1]=0; t2[r][2]=0; t2[r][3]=0; }
#pragma unroll 4
    for (int d = 0; d < 64; ++d){
        const float4 b0 = *(const float4*)&sKV[(d << 6) + 4*tj];
        const float4 b1 = *(const float4*)&sKV[(d << 6) + 4*tj + 32];
        const ull bb0 = pk(b0.x, b0.y), bb1 = pk(b0.z, b0.w);
        const ull bb2 = pk(b1.x, b1.y), bb3 = pk(b1.z, b1.w);
        const int dx = d ^ amask;
        const float a0 = sA[rb0 + dx], a1 = sA[rb1 + dx];
        const float a2 = sA[rb2 + dx], a3 = sA[rb3 + dx];
        const ull p0 = pk(a0,a0), p1 = pk(a1,a1), p2 = pk(a2,a2), p3 = pk(a3,a3);
        t2[0][0]=ffma2(p0,bb0,t2[0][0]); t2[0][1]=ffma2(p0,bb1,t2[0][1]);
        t2[0][2]=ffma2(p0,bb2,t2[0][2]); t2[0][3]=ffma2(p0,bb3,t2[0][3]);
        t2[1][0]=ffma2(p1,bb0,t2[1][0]); t2[1][1]=ffma2(p1,bb1,t2[1][1]);
        t2[1][2]=ffma2(p1,bb2,t2[1][2]); t2[1][3]=ffma2(p1,bb3,t2[1][3]);
        t2[2][0]=ffma2(p2,bb0,t2[2][0]); t2[2][1]=ffma2(p2,bb1,t2[2][1]);
        t2[2][2]=ffma2(p2,bb2,t2[2][2]); t2[2][3]=ffma2(p2,bb3,t2[2][3]);
        t2[3][0]=ffma2(p3,bb0,t2[3][0]); t2[3][1]=ffma2(p3,bb1,t2[3][1]);
        t2[3][2]=ffma2(p3,bb2,t2[3][2]); t2[3][3]=ffma2(p3,bb3,t2[3][3]);
        if (tj == 0){
            const float nd = sN[d];
            den0 = fmaf(a0, nd, den0); den1 = fmaf(a1, nd, den1);
            den2 = fmaf(a2, nd, den2); den3 = fmaf(a3, nd, den3);
        }
    }
    if (tj == 0){
        sI[4*ti]   = 1.0f / fmaxf(den0, EPSV);
        sI[4*ti+1] = 1.0f / fmaxf(den1, EPSV);
        sI[4*ti+2] = 1.0f / fmaxf(den2, EPSV);
        sI[4*ti+3] = 1.0f / fmaxf(den3, EPSV);
    }
}

__global__ void init_tail(const float* __restrict__ pkv,
                          const float* __restrict__ pnorm,
                          float* __restrict__ dout){
    int i = blockIdx.x * 256 + threadIdx.x;
    if (i < KV_SIZE)   dout[KV_OFF + i]   = pkv[i];
    if (i < NORM_SIZE) dout[NORM_OFF + i] = pnorm[i];
}

__global__ void __launch_bounds__(256, 2) fw_kernel(
    const float* __restrict__ keys, const float* __restrict__ values,
    const float* __restrict__ queries, const float* __restrict__ outin,
    const float* __restrict__ pkv, const float* __restrict__ pnorm,
    const float* __restrict__ gates, float* __restrict__ dout)
{
    extern __shared__ float sm[];
    float* sKV = sm;
    float* sA  = sm + S_A;
    float* sB  = sm + S_B;
    float* sN  = sm + S_N;
    float* sI  = sm + S_I;

    const int tid = threadIdx.x;
    const int bh  = blockIdx.y;
    const int ti  = tid >> 3;     // 0..31
    const int tj  = tid & 7;      // 0..7
    const size_t gOff = (size_t)bh * (8192 * 64);
    const int rowStart = blockIdx.x * 256;

    // ---- prologue: async load past_kv, past_norm, keys(chunk 0) ----
#pragma unroll
    for (int i = 0; i < 4; i++){
        int f = tid + (i << 8);
        cpa16(s2u(&sKV[f << 2]), &pkv[(size_t)bh*4096 + (f << 2)]);
    }
    if (tid < 16) cpa16(s2u(&sN[tid << 2]), &pnorm[bh*64 + (tid << 2)]);
    cp_tile(keys + gOff + (size_t)rowStart * 64, sA, tid);
    CP_COMMIT();

    const float et  = __expf(-gates[bh & 15]);
    const float gte = 1.f / (1.f + et);
    const float omg = et / (1.f + et);

    ull acc2[2][4];                // k^T v partial: d = 2*ti+dr, e cols {4tj..,4tj+32..}
#pragma unroll
    for (int a = 0; a < 2; a++)
#pragma unroll
        for (int b = 0; b < 4; b++) acc2[a][b] = 0ull;
    float nrm0 = 0.f, nrm1 = 0.f;

    for (int ch = 0; ch < 2; ++ch){
        const int row0 = rowStart + ch * 128;

        // async prefetch values(ch) into sB (consumed after GEMM1)
        cp_tile(values + gOff + (size_t)row0 * 64, sB, tid);
        CP_COMMIT();

        // ---- stage k: elu in place (same-thread RMW on cp.async'd data) ----
        CP_WAIT(1);                // keys(ch) landed; values(ch) may still fly
#pragma unroll
        for (int i = 0; i < 8; i++){
            int f = tid + (i << 8);
            int n = f >> 4, c4 = (f & 15) << 2;
            float4* p = (float4*)&sA[swz4(n, c4)];
            float4 v = *p;
            v.x = elu1(v.x); v.y = elu1(v.y); v.z = elu1(v.z); v.w = elu1(v.w);
            *p = v;
        }
        __syncthreads();

        // ---- GEMM1: delta = k @ past_kv ; denominators fused ----
        ull t2[4][4];
        gemm_qk(sA, sKV, sN, sI, t2, ti, tj);
        CP_WAIT(0);                // values(ch) landed
        __syncthreads();

        // ---- v = values - delta * inv  (in place in sB) ----
#pragma unroll
        for (int r = 0; r < 4; r++){
            const int row = 4*ti + r;
            const float inv = sI[row];
            float4* pa = (float4*)&sB[swz4(row, 4*tj)];
            float4* pb = (float4*)&sB[swz4(row, 4*tj + 32)];
            float4 va = *pa, vb = *pb;
            float m0,m1,m2,m3,m4,m5,m6,m7;
            upk(t2[r][0], m0, m1); upk(t2[r][1], m2, m3);
            upk(t2[r][2], m4, m5); upk(t2[r][3], m6, m7);
            va.x -= m0*inv; va.y -= m1*inv; va.z -= m2*inv; va.w -= m3*inv;
            vb.x -= m4*inv; vb.y -= m5*inv; vb.z -= m6*inv; vb.w -= m7*inv;
            *pa = va; *pb = vb;
        }
        __syncthreads();

        // ---- GEMM2: acc += k^T v ; new_norm fused on tj==0 ----
        {
            const int ca = 2*ti;
#pragma unroll 4
            for (int n = 0; n < 128; ++n){
                const float2 a  = *(const float2*)&sA[swz4(n, ca)];
                const float4 v0 = *(const float4*)&sB[swz4(n, 4*tj)];
                const float4 v1 = *(const float4*)&sB[swz4(n, 4*tj + 32)];
                const ull b0 = pk(v0.x, v0.y), b1 = pk(v0.z, v0.w);
                const ull b2 = pk(v1.x, v1.y), b3 = pk(v1.z, v1.w);
                const ull ax = pk(a.x, a.x), ay = pk(a.y, a.y);
                acc2[0][0]=ffma2(ax,b0,acc2[0][0]); acc2[0][1]=ffma2(ax,b1,acc2[0][1]);
                acc2[0][2]=ffma2(ax,b2,acc2[0][2]); acc2[0][3]=ffma2(ax,b3,acc2[0][3]);
                acc2[1][0]=ffma2(ay,b0,acc2[1][0]); acc2[1][1]=ffma2(ay,b1,acc2[1][1]);
                acc2[1][2]=ffma2(ay,b2,acc2[1][2]); acc2[1][3]=ffma2(ay,b3,acc2[1][3]);
                if (tj == 0){ nrm0 += a.x; nrm1 += a.y; }
            }
        }
        __syncthreads();

        // async prefetch keys(ch+1) into sA (sA free after GEMM2)
        if (ch == 0){
            cp_tile(keys + gOff + (size_t)(rowStart + 128) * 64, sA, tid);
            CP_COMMIT();
        }

        // ---- stage q = elu(queries)+1 into sB (v consumed by GEMM2) ----
#pragma unroll
        for (int i = 0; i < 8; i++){
            int f = tid + (i << 8);
            int n = f >> 4, c4 = (f & 15) << 2;
            float4 v = *(const float4*)&queries[gOff + (size_t)(row0 + n) * 64 + c4];
            v.x = elu1(v.x); v.y = elu1(v.y); v.z = elu1(v.z); v.w = elu1(v.w);
            *(float4*)&sB[swz4(n, c4)] = v;
        }
        __syncthreads();

        // ---- GEMM3: mem = q @ past_kv ; q-denominators fused ----
        gemm_qk(sB, sKV, sN, sI, t2, ti, tj);
        __syncthreads();

        // ---- epilogue: out_g = out*g + mem*inv*(1-g) ----
#pragma unroll
        for (int r = 0; r < 4; r++){
            const int row = 4*ti + r;
            const float s = sI[row] * omg;
            const float* go = &outin[gOff + (size_t)(row0 + row) * 64];
            float4 oa = *(const float4*)&go[4*tj];
            float4 ob = *(const float4*)&go[4*tj + 32];
            float m0,m1,m2,m3,m4,m5,m6,m7;
            upk(t2[r][0], m0, m1); upk(t2[r][1], m2, m3);
            upk(t2[r][2], m4, m5); upk(t2[r][3], m6, m7);
            oa.x = oa.x*gte + m0*s; oa.y = oa.y*gte + m1*s;
            oa.z = oa.z*gte + m2*s; oa.w = oa.w*gte + m3*s;
            ob.x = ob.x*gte + m4*s; ob.y = ob.y*gte + m5*s;
            ob.z = ob.z*gte + m6*s; ob.w = ob.w*gte + m7*s;
            float* po = &dout[gOff + (size_t)(row0 + row) * 64];
            *(float4*)&po[4*tj]      = oa;
            *(float4*)&po[4*tj + 32] = ob;
        }
    }

    // ---- flush block partials of new_kv / new_norm ----
    float* kvout = dout + KV_OFF + bh * 4096;
#pragma unroll
    for (int dr = 0; dr < 2; dr++){
        float* rowp = &kvout[(2*ti + dr) * 64];
        float lo, hi;
        upk(acc2[dr][0], lo, hi); atomicAdd(&rowp[4*tj],      lo); atomicAdd(&rowp[4*tj+1],  hi);
        upk(acc2[dr][1], lo, hi); atomicAdd(&rowp[4*tj+2],    lo); atomicAdd(&rowp[4*tj+3],  hi);
        upk(acc2[dr][2], lo, hi); atomicAdd(&rowp[4*tj+32],   lo); atomicAdd(&rowp[4*tj+33], hi);
        upk(acc2[dr][3], lo, hi); atomicAdd(&rowp[4*tj+34],   lo); atomicAdd(&rowp[4*tj+35], hi);
    }
    if (tj == 0){
        atomicAdd(&dout[NORM_OFF + bh*64 + 2*ti],     nrm0);
        atomicAdd(&dout[NORM_OFF + bh*64 + 2*ti + 1], nrm1);
    }
}

extern "C" void kernel_launch(void* const* d_in, const int* in_sizes, int n_in,
                              void* d_out, int out_size)
{
    const float* keys    = (const float*)d_in[0];
    const float* values  = (const float*)d_in[1];
    const float* queries = (const float*)d_in[2];
    const float* outin   = (const float*)d_in[3];
    const float* pkv     = (const float*)d_in[4];
    const float* pnorm   = (const float*)d_in[5];
    const float* gates   = (const float*)d_in[6];
    float* dout = (float*)d_out;

    cudaFuncSetAttribute(fw_kernel, cudaFuncAttributeMaxDynamicSharedMemorySize, SMEM_BYTES);

    init_tail<<<1024, 256>>>(pkv, pnorm, dout);
    fw_kernel<<<dim3(32, 64), 256, SMEM_BYTES>>>(keys, values, queries, outin,
                                                 pkv, pnorm, gates, dout);
}

// round 3
// speedup vs baseline: 1.9103x; 1.5415x over previous
#include <cuda_runtime.h>
#include <cstdint>

#define KV_OFF   (64*8192*64)
#define KV_SIZE  (64*64*64)
#define NORM_OFF (KV_OFF + KV_SIZE)
#define NORM_SIZE (64*64)
#define EPSV 1e-10f

#define S 68                    // padded row stride (floats): conflict-free banks
#define O_KV 0                  // 64 x S
#define O_K  4352               // 128 x S
#define O_V  13056              // 128 x S
#define O_N  21760              // 64
#define O_I  21824              // 128
#define SMEM_FLOATS 21952
#define SMEM_BYTES (SMEM_FLOATS*4)

__device__ __forceinline__ float elu1(float x){ return x > 0.f ? x + 1.f : __expf(x); }
__device__ __forceinline__ float t32(float x){
    uint32_t u; asm("cvt.rna.tf32.f32 %0, %1;" : "=r"(u) : "f"(x));
    return __uint_as_float(u);
}
__device__ __forceinline__ uint32_t s2u(const void* p){
    return (uint32_t)__cvta_generic_to_shared(p);
}
__device__ __forceinline__ void cpa16(uint32_t s, const void* g){
    asm volatile("cp.async.cg.shared.global [%0], [%1], 16;" :: "r"(s), "l"(g));
}
#define CP_COMMIT() asm volatile("cp.async.commit_group;")
#define CP_WAIT(n)  asm volatile("cp.async.wait_group %0;" :: "n"(n))

__device__ __forceinline__ void mma_tf32(float& c0, float& c1, float& c2, float& c3,
                                         uint32_t a0, uint32_t a1, uint32_t a2, uint32_t a3,
                                         uint32_t b0, uint32_t b1){
    asm("mma.sync.aligned.m16n8k8.row.col.f32.tf32.tf32.f32 "
        "{%0,%1,%2,%3},{%4,%5,%6,%7},{%8,%9},{%0,%1,%2,%3};"
        : "+f"(c0), "+f"(c1), "+f"(c2), "+f"(c3)
        : "r"(a0), "r"(a1), "r"(a2), "r"(a3), "r"(b0), "r"(b1));
}

// async-copy one 128x64 fp32 tile gmem -> padded smem
__device__ __forceinline__ void cp_tile(const float* __restrict__ g,
                                        float* __restrict__ s, int tid){
#pragma unroll
    for (int i = 0; i < 8; i++){
        int f = tid + (i << 8);
        int n = f >> 4, c4 = (f & 15) << 2;
        cpa16(s2u(&s[n*S + c4]), &g[(n << 6) + c4]);
    }
}

// elu + tf32-round in place (same thread chunks as cp_tile -> own-wait suffices)
__device__ __forceinline__ void elu_cvt_tile(float* __restrict__ s, int tid){
#pragma unroll
    for (int i = 0; i < 8; i++){
        int f = tid + (i << 8);
        int n = f >> 4, c4 = (f & 15) << 2;
        float4* p = (float4*)&s[n*S + c4];
        float4 v = *p;
        v.x = t32(elu1(v.x)); v.y = t32(elu1(v.y));
        v.z = t32(elu1(v.z)); v.w = t32(elu1(v.w));
        *p = v;
    }
}

// denominators for 128 rows of sX (dot with sN) -> reciprocals in sI;
// optionally accumulate column sums (new_norm partials) into nrm.
__device__ __forceinline__ void denom_pass(const float* __restrict__ sX,
                                           const float* __restrict__ sN,
                                           float* __restrict__ sI,
                                           int tid, bool donorm, float& nrm){
    const int row = tid >> 1, half = tid & 1;
    const float* base = sX + row*S + half*32;
    float s0 = 0.f;
#pragma unroll
    for (int j = 0; j < 8; j++){
        float4 a = *(const float4*)&base[4*j];
        const float* nb = &sN[half*32 + 4*j];
        s0 = fmaf(a.x, nb[0], s0); s0 = fmaf(a.y, nb[1], s0);
        s0 = fmaf(a.z, nb[2], s0); s0 = fmaf(a.w, nb[3], s0);
    }
    s0 += __shfl_xor_sync(0xffffffffu, s0, 1);
    if (half == 0) sI[row] = 1.0f / fmaxf(s0, EPSV);
    if (donorm){
        const int d = tid & 63, grp = tid >> 6;
        const float* cb = sX + (grp*32)*S + d;
        float t = 0.f;
#pragma unroll 8
        for (int r = 0; r < 32; r++) t += cb[r*S];
        nrm += t;
    }
}

// C[16 x 64] = A(rows n0..n0+15 of sA) @ sKV   (8 ntiles x 8 ksteps of m16n8k8)
__device__ __forceinline__ void gemm_row(const uint32_t* __restrict__ sA,
                                         const uint32_t* __restrict__ sKVu,
                                         float (&c)[8][4], int n0, int gid, int tig){
#pragma unroll
    for (int nt = 0; nt < 8; nt++){ c[nt][0]=0.f; c[nt][1]=0.f; c[nt][2]=0.f; c[nt][3]=0.f; }
#pragma unroll
    for (int k0 = 0; k0 < 64; k0 += 8){
        const uint32_t a0 = sA[(n0+gid)*S   + k0+tig];
        const uint32_t a1 = sA[(n0+gid+8)*S + k0+tig];
        const uint32_t a2 = sA[(n0+gid)*S   + k0+tig+4];
        const uint32_t a3 = sA[(n0+gid+8)*S + k0+tig+4];
        const uint32_t* bq0 = &sKVu[(k0+tig)*S   + gid];
        const uint32_t* bq1 = &sKVu[(k0+tig+4)*S + gid];
#pragma unroll
        for (int nt = 0; nt < 8; nt++)
            mma_tf32(c[nt][0], c[nt][1], c[nt][2], c[nt][3],
                     a0, a1, a2, a3, bq0[8*nt], bq1[8*nt]);
    }
}

__global__ void init_tail(const float* __restrict__ pkv,
                          const float* __restrict__ pnorm,
                          float* __restrict__ dout){
    int i = blockIdx.x * 256 + threadIdx.x;
    if (i < KV_SIZE)   dout[KV_OFF + i]   = pkv[i];
    if (i < NORM_SIZE) dout[NORM_OFF + i] = pnorm[i];
}

__global__ void __launch_bounds__(256, 2) fw_kernel(
    const float* __restrict__ keys, const float* __restrict__ values,
    const float* __restrict__ queries, const float* __restrict__ outin,
    const float* __restrict__ pkv, const float* __restrict__ pnorm,
    const float* __restrict__ gates, float* __restrict__ dout)
{
    extern __shared__ float sm[];
    float* sKV = sm + O_KV;
    float* sK  = sm + O_K;
    float* sV  = sm + O_V;
    float* sN  = sm + O_N;
    float* sI  = sm + O_I;
    const uint32_t* sKVu = (const uint32_t*)sKV;
    const uint32_t* sKu  = (const uint32_t*)sK;
    const uint32_t* sVu  = (const uint32_t*)sV;

    const int tid  = threadIdx.x;
    const int warp = tid >> 5, lane = tid & 31;
    const int gid  = lane >> 2, tig = lane & 3;
    const int bh   = blockIdx.y;
    const size_t gOff = (size_t)bh * (8192 * 64);
    const int rowStart = blockIdx.x * 256;
    const int n0 = warp << 4;                 // GEMM1/3 row base
    const int m0 = (warp & 3) << 4;           // GEMM2 d base
    const int col0 = (warp >> 2) << 5;        // GEMM2 e base

    // ---- prologue: cp KV+norm (group 0), keys(chunk0) (group 1) ----
#pragma unroll
    for (int i = 0; i < 4; i++){
        int f = tid + (i << 8);
        int n = f >> 4, c4 = (f & 15) << 2;
        cpa16(s2u(&sKV[n*S + c4]), &pkv[(size_t)bh*4096 + (n << 6) + c4]);
    }
    if (tid < 16) cpa16(s2u(&sN[tid << 2]), &pnorm[bh*64 + (tid << 2)]);
    CP_COMMIT();
    cp_tile(keys + gOff + (size_t)rowStart * 64, sK, tid);
    CP_COMMIT();

    const float et  = __expf(-gates[bh & 15]);
    const float gte = 1.f / (1.f + et);
    const float omg = et / (1.f + et);

    // cvt KV to tf32 in place (own cp chunks; group0 done after wait<=1)
    CP_WAIT(1);
#pragma unroll
    for (int i = 0; i < 4; i++){
        int f = tid + (i << 8);
        int n = f >> 4, c4 = (f & 15) << 2;
        float4* p = (float4*)&sKV[n*S + c4];
        float4 v = *p;
        v.x = t32(v.x); v.y = t32(v.y); v.z = t32(v.z); v.w = t32(v.w);
        *p = v;
    }

    float acc[4][4];                          // persistent k^T v frags
#pragma unroll
    for (int a = 0; a < 4; a++){ acc[a][0]=0.f; acc[a][1]=0.f; acc[a][2]=0.f; acc[a][3]=0.f; }
    float nrm = 0.f;
    float c[8][4];

    for (int ch = 0; ch < 2; ++ch){
        const int row0 = rowStart + ch * 128;

        // prefetch values(ch) -> sV
        cp_tile(values + gOff + (size_t)row0 * 64, sV, tid);
        CP_COMMIT();

        // keys(ch) landed (all but newest group); elu+cvt in place
        CP_WAIT(1);
        elu_cvt_tile(sK, tid);
        __syncthreads();

        // denominators (+ new_norm column partials)
        denom_pass(sK, sN, sI, tid, true, nrm);
        __syncthreads();

        // ---- GEMM1: delta = k @ KV ----
        gemm_row(sKu, sKVu, c, n0, gid, tig);

        CP_WAIT(0);
        __syncthreads();                      // values visible to all

        // ---- frag-wise: v = values - delta*inv, cvt tf32, in place in sV ----
        {
            const float i1 = sI[n0 + gid], i2 = sI[n0 + gid + 8];
#pragma unroll
            for (int nt = 0; nt < 8; nt++){
                const int cc = 8*nt + 2*tig;
                float2* p1 = (float2*)&sV[(n0+gid)*S + cc];
                float2* p2 = (float2*)&sV[(n0+gid+8)*S + cc];
                float2 v1 = *p1, v2 = *p2;
                v1.x = t32(v1.x - c[nt][0]*i1); v1.y = t32(v1.y - c[nt][1]*i1);
                v2.x = t32(v2.x - c[nt][2]*i2); v2.y = t32(v2.y - c[nt][3]*i2);
                *p1 = v1; *p2 = v2;
            }
        }
        __syncthreads();

        // ---- GEMM2: acc += k^T v  (A = k^T from sK, B = v from sV) ----
#pragma unroll 2
        for (int k0 = 0; k0 < 128; k0 += 8){
            const uint32_t a0 = sKu[(k0+tig)*S   + m0+gid];
            const uint32_t a1 = sKu[(k0+tig)*S   + m0+gid+8];
            const uint32_t a2 = sKu[(k0+tig+4)*S + m0+gid];
            const uint32_t a3 = sKu[(k0+tig+4)*S + m0+gid+8];
            const uint32_t* bq0 = &sVu[(k0+tig)*S   + col0 + gid];
            const uint32_t* bq1 = &sVu[(k0+tig+4)*S + col0 + gid];
#pragma unroll
            for (int j = 0; j < 4; j++)
                mma_tf32(acc[j][0], acc[j][1], acc[j][2], acc[j][3],
                         a0, a1, a2, a3, bq0[8*j], bq1[8*j]);
        }
        __syncthreads();

        // prefetch keys(ch+1) -> sK
        if (ch == 0){
            cp_tile(keys + gOff + (size_t)(rowStart + 128) * 64, sK, tid);
            CP_COMMIT();
        }

        // stage q = elu(queries)+1 (tf32) -> sV
#pragma unroll
        for (int i = 0; i < 8; i++){
            int f = tid + (i << 8);
            int n = f >> 4, c4 = (f & 15) << 2;
            float4 v = *(const float4*)&queries[gOff + (size_t)(row0 + n) * 64 + c4];
            v.x = t32(elu1(v.x)); v.y = t32(elu1(v.y));
            v.z = t32(elu1(v.z)); v.w = t32(elu1(v.w));
            *(float4*)&sV[n*S + c4] = v;
        }
        __syncthreads();

        denom_pass(sV, sN, sI, tid, false, nrm);
        __syncthreads();

        // ---- GEMM3: mem = q @ KV ----
        gemm_row(sVu, sKVu, c, n0, gid, tig);

        // ---- frag-wise epilogue: out_g = out*g + mem*inv*(1-g) ----
        {
            const float s1 = sI[n0 + gid] * omg, s2 = sI[n0 + gid + 8] * omg;
            const size_t r1 = gOff + (size_t)(row0 + n0 + gid) * 64;
            const size_t r2 = gOff + (size_t)(row0 + n0 + gid + 8) * 64;
#pragma unroll
            for (int nt = 0; nt < 8; nt++){
                const int cc = 8*nt + 2*tig;
                float2 o1 = *(const float2*)&outin[r1 + cc];
                float2 o2 = *(const float2*)&outin[r2 + cc];
                o1.x = o1.x*gte + c[nt][0]*s1; o1.y = o1.y*gte + c[nt][1]*s1;
                o2.x = o2.x*gte + c[nt][2]*s2; o2.y = o2.y*gte + c[nt][3]*s2;
                *(float2*)&dout[r1 + cc] = o1;
                *(float2*)&dout[r2 + cc] = o2;
            }
        }
        __syncthreads();                      // sV/sI reuse next chunk
    }

    // ---- flush new_kv / new_norm partials ----
    float* kvout = dout + KV_OFF + bh * 4096;
#pragma unroll
    for (int j = 0; j < 4; j++){
        const int cc = col0 + 8*j + 2*tig;
        atomicAdd(&kvout[(m0+gid)*64   + cc],     acc[j][0]);
        atomicAdd(&kvout[(m0+gid)*64   + cc + 1], acc[j][1]);
        atomicAdd(&kvout[(m0+gid+8)*64 + cc],     acc[j][2]);
        atomicAdd(&kvout[(m0+gid+8)*64 + cc + 1], acc[j][3]);
    }
    atomicAdd(&dout[NORM_OFF + bh*64 + (tid & 63)], nrm);
}

extern "C" void kernel_launch(void* const* d_in, const int* in_sizes, int n_in,
                              void* d_out, int out_size)
{
    const float* keys    = (const float*)d_in[0];
    const float* values  = (const float*)d_in[1];
    const float* queries = (const float*)d_in[2];
    const float* outin   = (const float*)d_in[3];
    const float* pkv     = (const float*)d_in[4];
    const float* pnorm   = (const float*)d_in[5];
    const float* gates   = (const float*)d_in[6];
    float* dout = (float*)d_out;

    cudaFuncSetAttribute(fw_kernel, cudaFuncAttributeMaxDynamicSharedMemorySize, SMEM_BYTES);

    init_tail<<<1024, 256>>>(pkv, pnorm, dout);
    fw_kernel<<<dim3(32, 64), 256, SMEM_BYTES>>>(keys, values, queries, outin,
                                                 pkv, pnorm, gates, dout);
}

// round 4
// speedup vs baseline: 2.0049x; 1.0495x over previous
#include <cuda_runtime.h>
#include <cstdint>

#define KV_OFF   (64*8192*64)
#define KV_SIZE  (64*64*64)
#define NORM_OFF (KV_OFF + KV_SIZE)
#define EPSV 1e-10f
#define S 68                     // padded row stride (floats)

// float offsets in dynamic smem
#define O_KV   0                 // 64 x S past_kv (tf32)
#define O_K0   4352              // group0 K tile 64 x S
#define O_K1   8704              // group1 K tile
#define O_V0   13056             // group0 V/q tile
#define O_V1   17408             // group1 V/q tile
#define O_N    21760             // 64 past_norm
#define O_I0   21824             // 64 reciprocal denoms group0
#define O_I1   21888             // group1
#define O_NRM  21952             // 64 new_norm partials (shared atomics)
#define SMEM_FLOATS 22016
#define SMEM_BYTES (SMEM_FLOATS*4)

__device__ __forceinline__ float elu1(float x){ return x > 0.f ? x + 1.f : __expf(x); }
__device__ __forceinline__ float t32(float x){
    uint32_t u; asm("cvt.rna.tf32.f32 %0, %1;" : "=r"(u) : "f"(x));
    return __uint_as_float(u);
}
__device__ __forceinline__ uint32_t s2u(const void* p){
    return (uint32_t)__cvta_generic_to_shared(p);
}
__device__ __forceinline__ void cpa16(uint32_t s, const void* g){
    asm volatile("cp.async.cg.shared.global [%0], [%1], 16;" :: "r"(s), "l"(g));
}
#define CP_COMMIT() asm volatile("cp.async.commit_group;")
#define CP_WAIT(n)  asm volatile("cp.async.wait_group %0;" :: "n"(n))
__device__ __forceinline__ void barg(int id){ asm volatile("bar.sync %0, 128;" :: "r"(id) : "memory"); }
__device__ __forceinline__ void barall(){ asm volatile("bar.sync 0, 256;" ::: "memory"); }

__device__ __forceinline__ void mma_tf32(float& c0, float& c1, float& c2, float& c3,
                                         uint32_t a0, uint32_t a1, uint32_t a2, uint32_t a3,
                                         uint32_t b0, uint32_t b1){
    asm("mma.sync.aligned.m16n8k8.row.col.f32.tf32.tf32.f32 "
        "{%0,%1,%2,%3},{%4,%5,%6,%7},{%8,%9},{%0,%1,%2,%3};"
        : "+f"(c0), "+f"(c1), "+f"(c2), "+f"(c3)
        : "r"(a0), "r"(a1), "r"(a2), "r"(a3), "r"(b0), "r"(b1));
}

// async-copy one 64x64 fp32 tile gmem -> padded smem (128 threads)
__device__ __forceinline__ void cp_tile64(const float* __restrict__ g,
                                          float* __restrict__ s, int tg){
#pragma unroll
    for (int i = 0; i < 8; i++){
        int f = tg + (i << 7);
        int n = f >> 4, c4 = (f & 15) << 2;
        cpa16(s2u(&s[n*S + c4]), &g[(n << 6) + c4]);
    }
}
// elu + tf32 round in place (same per-thread chunks as cp_tile64)
__device__ __forceinline__ void elu_cvt64(float* __restrict__ s, int tg){
#pragma unroll
    for (int i = 0; i < 8; i++){
        int f = tg + (i << 7);
        int n = f >> 4, c4 = (f & 15) << 2;
        float4* p = (float4*)&s[n*S + c4];
        float4 v = *p;
        v.x = t32(elu1(v.x)); v.y = t32(elu1(v.y));
        v.z = t32(elu1(v.z)); v.w = t32(elu1(v.w));
        *p = v;
    }
}

// denominators for 64 rows (dot with sN) -> reciprocals in sI; opt. column sums
__device__ __forceinline__ void denom64(const float* __restrict__ sX,
                                        const float* __restrict__ sN,
                                        float* __restrict__ sI,
                                        int tg, bool donorm, float& nrm){
    const int row = tg >> 1, half = tg & 1;
    const float* base = sX + row*S + half*32;
    float s0 = 0.f;
#pragma unroll
    for (int j = 0; j < 8; j++){
        float4 a = *(const float4*)&base[4*j];
        const float* nb = &sN[half*32 + 4*j];
        s0 = fmaf(a.x, nb[0], s0); s0 = fmaf(a.y, nb[1], s0);
        s0 = fmaf(a.z, nb[2], s0); s0 = fmaf(a.w, nb[3], s0);
    }
    s0 += __shfl_xor_sync(0xffffffffu, s0, 1);
    if (half == 0) sI[row] = 1.0f / fmaxf(s0, EPSV);
    if (donorm){
        const int col = tg & 63;
        const float* cb = sX + ((tg >> 6) * 32) * S + col;
        float t = 0.f;
#pragma unroll 8
        for (int r = 0; r < 32; r++) t += cb[r*S];
        nrm += t;
    }
}

// C[16 x 32] = A(rows n0..+15) @ KV(cols 32*pass..+31): 4 ntiles x 8 ksteps
__device__ __forceinline__ void gemm_pass(const uint32_t* __restrict__ sA,
                                          const uint32_t* __restrict__ sB,
                                          float (&c)[4][4], int n0, int gid, int tig, int pass){
#pragma unroll
    for (int nt = 0; nt < 4; nt++){ c[nt][0]=0.f; c[nt][1]=0.f; c[nt][2]=0.f; c[nt][3]=0.f; }
#pragma unroll
    for (int ks = 0; ks < 8; ks++){
        const int k = 8*ks;
        const uint32_t a0 = sA[(n0+gid)*S   + k+tig];
        const uint32_t a1 = sA[(n0+gid+8)*S + k+tig];
        const uint32_t a2 = sA[(n0+gid)*S   + k+tig+4];
        const uint32_t a3 = sA[(n0+gid+8)*S + k+tig+4];
        const uint32_t* bq0 = &sB[(k+tig)*S   + 32*pass + gid];
        const uint32_t* bq1 = &sB[(k+tig+4)*S + 32*pass + gid];
#pragma unroll
        for (int nt = 0; nt < 4; nt++)
            mma_tf32(c[nt][0], c[nt][1], c[nt][2], c[nt][3],
                     a0, a1, a2, a3, bq0[8*nt], bq1[8*nt]);
    }
}

__global__ void init_tail(const float* __restrict__ pkv,
                          const float* __restrict__ pnorm,
                          float* __restrict__ dout){
    int i = blockIdx.x * 256 + threadIdx.x;
    if (i < KV_SIZE)          dout[KV_OFF + i]   = pkv[i];
    if (i < 64*64)            dout[NORM_OFF + i] = pnorm[i];
}

__global__ void __launch_bounds__(256, 2) fw_kernel(
    const float* __restrict__ keys, const float* __restrict__ values,
    const float* __restrict__ queries, const float* __restrict__ outin,
    const float* __restrict__ pkv, const float* __restrict__ pnorm,
    const float* __restrict__ gates, float* __restrict__ dout)
{
    extern __shared__ float sm[];
    float* sKV = sm + O_KV;
    float* sN  = sm + O_N;
    float* sNrm= sm + O_NRM;
    const uint32_t* sKVu = (const uint32_t*)sKV;

    const int tid  = threadIdx.x;
    const int g    = tid >> 7;           // warpgroup 0/1
    const int tg   = tid & 127;
    const int warp = tid >> 5, lane = tid & 31;
    const int wg   = warp & 3;           // warp within group
    const int gid  = lane >> 2, tig = lane & 3;
    const int n0   = wg << 4;            // row/d base for this warp
    const int bh   = blockIdx.y;
    const size_t gOff = (size_t)bh * (8192 * 64);
    const int rowBase = blockIdx.x * 256 + (g << 7);

    float* sKg = sm + (g ? O_K1 : O_K0);
    float* sVg = sm + (g ? O_V1 : O_V0);
    float* sIg = sm + (g ? O_I1 : O_I0);
    const uint32_t* sKu = (const uint32_t*)sKg;
    const uint32_t* sVu = (const uint32_t*)sVg;
    const int bid = 1 + g;               // named barrier id for this group

    // ---- prologue: KV + norm (all 256), then group K(chunk0) ----
#pragma unroll
    for (int i = 0; i < 4; i++){
        int f = tid + (i << 8);
        int n = f >> 4, c4 = (f & 15) << 2;
        cpa16(s2u(&sKV[n*S + c4]), &pkv[(size_t)bh*4096 + (n << 6) + c4]);
    }
    if (tid < 16) cpa16(s2u(&sN[tid << 2]), &pnorm[bh*64 + (tid << 2)]);
    if (tid < 64) sNrm[tid] = 0.f;
    CP_COMMIT();
    cp_tile64(keys + gOff + (size_t)rowBase * 64, sKg, tg);
    CP_COMMIT();

    const float et  = __expf(-gates[bh & 15]);
    const float gte = 1.f / (1.f + et);
    const float omg = et / (1.f + et);

    CP_WAIT(1);                          // KV landed (K may still fly)
#pragma unroll
    for (int i = 0; i < 4; i++){
        int f = tid + (i << 8);
        int n = f >> 4, c4 = (f & 15) << 2;
        float4* p = (float4*)&sKV[n*S + c4];
        float4 v = *p;
        v.x = t32(v.x); v.y = t32(v.y); v.z = t32(v.z); v.w = t32(v.w);
        *p = v;
    }
    barall();

    float acc[8][4];                     // persistent k^T v partials (16d x 64e)
#pragma unroll
    for (int a = 0; a < 8; a++){ acc[a][0]=0.f; acc[a][1]=0.f; acc[a][2]=0.f; acc[a][3]=0.f; }
    float nrm = 0.f;
    float c[4][4];

    for (int ch = 0; ch < 2; ++ch){
        const int row0 = rowBase + (ch << 6);

        cp_tile64(values + gOff + (size_t)row0 * 64, sVg, tg);
        CP_COMMIT();

        CP_WAIT(1);                      // K(ch) landed
        elu_cvt64(sKg, tg);
        barg(bid);
        denom64(sKg, sN, sIg, tg, true, nrm);
        barg(bid);

        // ---- GEMM1 in two 32-col passes, fused v-update ----
#pragma unroll
        for (int pass = 0; pass < 2; pass++){
            gemm_pass(sKu, sKVu, c, n0, gid, tig, pass);
            if (pass == 0){ CP_WAIT(0); barg(bid); }   // values visible
            const float i1 = sIg[n0 + gid], i2 = sIg[n0 + gid + 8];
#pragma unroll
            for (int nt = 0; nt < 4; nt++){
                const int cc = 32*pass + 8*nt + 2*tig;
                float2* p1 = (float2*)&sVg[(n0+gid)*S + cc];
                float2* p2 = (float2*)&sVg[(n0+gid+8)*S + cc];
                float2 v1 = *p1, v2 = *p2;
                v1.x = t32(v1.x - c[nt][0]*i1); v1.y = t32(v1.y - c[nt][1]*i1);
                v2.x = t32(v2.x - c[nt][2]*i2); v2.y = t32(v2.y - c[nt][3]*i2);
                *p1 = v1; *p2 = v2;
            }
        }
        barg(bid);

        // ---- GEMM2: acc += k^T v over this chunk's 64 rows ----
#pragma unroll 2
        for (int k0 = 0; k0 < 64; k0 += 8){
            const uint32_t a0 = sKu[(k0+tig)*S   + n0+gid];
            const uint32_t a1 = sKu[(k0+tig)*S   + n0+gid+8];
            const uint32_t a2 = sKu[(k0+tig+4)*S + n0+gid];
            const uint32_t a3 = sKu[(k0+tig+4)*S + n0+gid+8];
            const uint32_t* bq0 = &sVu[(k0+tig)*S   + gid];
            const uint32_t* bq1 = &sVu[(k0+tig+4)*S + gid];
#pragma unroll
            for (int nt = 0; nt < 8; nt++)
                mma_tf32(acc[nt][0], acc[nt][1], acc[nt][2], acc[nt][3],
                         a0, a1, a2, a3, bq0[8*nt], bq1[8*nt]);
        }
        barg(bid);

        if (ch == 0){
            cp_tile64(keys + gOff + (size_t)(row0 + 64) * 64, sKg, tg);
            CP_COMMIT();
        }

        // ---- stage q = elu(queries)+1 (tf32) into sVg ----
#pragma unroll
        for (int i = 0; i < 8; i++){
            int f = tg + (i << 7);
            int n = f >> 4, c4 = (f & 15) << 2;
            float4 v = *(const float4*)&queries[gOff + (size_t)(row0 + n) * 64 + c4];
            v.x = t32(elu1(v.x)); v.y = t32(elu1(v.y));
            v.z = t32(elu1(v.z)); v.w = t32(elu1(v.w));
            *(float4*)&sVg[n*S + c4] = v;
        }
        barg(bid);
        denom64(sVg, sN, sIg, tg, false, nrm);
        barg(bid);

        // ---- GEMM3 in two passes, fused gated epilogue ----
#pragma unroll
        for (int pass = 0; pass < 2; pass++){
            gemm_pass(sVu, sKVu, c, n0, gid, tig, pass);
            const float s1 = sIg[n0 + gid] * omg, s2 = sIg[n0 + gid + 8] * omg;
            const size_t r1 = gOff + (size_t)(row0 + n0 + gid) * 64;
            const size_t r2 = gOff + (size_t)(row0 + n0 + gid + 8) * 64;
#pragma unroll
            for (int nt = 0; nt < 4; nt++){
                const int cc = 32*pass + 8*nt + 2*tig;
                float2 o1 = *(const float2*)&outin[r1 + cc];
                float2 o2 = *(const float2*)&outin[r2 + cc];
                o1.x = o1.x*gte + c[nt][0]*s1; o1.y = o1.y*gte + c[nt][1]*s1;
                o2.x = o2.x*gte + c[nt][2]*s2; o2.y = o2.y*gte + c[nt][3]*s2;
                *(float2*)&dout[r1 + cc] = o1;
                *(float2*)&dout[r2 + cc] = o2;
            }
        }
        barg(bid);                       // sVg / sIg reused next chunk
    }

    // ---- combine groups' acc in smem, then single atomic flush ----
    atomicAdd(&sNrm[tg & 63], nrm);
    barall();
    float* sComb = sm + O_K0;            // group0 K buffer, dead now
    if (g == 0){
#pragma unroll
        for (int nt = 0; nt < 8; nt++){
            const int cc = 8*nt + 2*tig;
            sComb[(n0+gid)*64   + cc]     = acc[nt][0];
            sComb[(n0+gid)*64   + cc + 1] = acc[nt][1];
            sComb[(n0+gid+8)*64 + cc]     = acc[nt][2];
            sComb[(n0+gid+8)*64 + cc + 1] = acc[nt][3];
        }
    }
    barall();
    if (g == 1){
#pragma unroll
        for (int nt = 0; nt < 8; nt++){
            const int cc = 8*nt + 2*tig;
            sComb[(n0+gid)*64   + cc]     += acc[nt][0];
            sComb[(n0+gid)*64   + cc + 1] += acc[nt][1];
            sComb[(n0+gid+8)*64 + cc]     += acc[nt][2];
            sComb[(n0+gid+8)*64 + cc + 1] += acc[nt][3];
        }
    }
    barall();
    float* kvout = dout + KV_OFF + bh * 4096;
#pragma unroll
    for (int k = 0; k < 16; k++){
        const int idx = tid + (k << 8);
        atomicAdd(&kvout[idx], sComb[idx]);
    }
    if (tid < 64) atomicAdd(&dout[NORM_OFF + bh*64 + tid], sNrm[tid]);
}

extern "C" void kernel_launch(void* const* d_in, const int* in_sizes, int n_in,
                              void* d_out, int out_size)
{
    const float* keys    = (const float*)d_in[0];
    const float* values  = (const float*)d_in[1];
    const float* queries = (const float*)d_in[2];
    const float* outin   = (const float*)d_in[3];
    const float* pkv     = (const float*)d_in[4];
    const float* pnorm   = (const float*)d_in[5];
    const float* gates   = (const float*)d_in[6];
    float* dout = (float*)d_out;

    cudaFuncSetAttribute(fw_kernel, cudaFuncAttributeMaxDynamicSharedMemorySize, SMEM_BYTES);

    init_tail<<<1024, 256>>>(pkv, pnorm, dout);
    fw_kernel<<<dim3(32, 64), 256, SMEM_BYTES>>>(keys, values, queries, outin,
                                                 pkv, pnorm, gates, dout);
}

// round 5
// speedup vs baseline: 2.5047x; 1.2493x over previous
#include <cuda_runtime.h>
#include <cuda_fp16.h>
#include <cstdint>

#define KV_OFF   (64*8192*64)
#define KV_SIZE  (64*64*64)
#define NORM_OFF (KV_OFF + KV_SIZE)
#define EPSV 1e-10f
#define SH 72                     // halves per tile row (144B: conflict-free ldmatrix)

// half-unit offsets in dynamic smem
#define H_KV 0                    // 64 x SH past_kv
#define H_K0 4608
#define H_K1 9216
#define H_V0 13824
#define H_V1 18432
#define F_BASE_BYTES 46080        // float region: sN[64], sI0[64], sI1[64], sNrm[64]
#define SMEM_BYTES (F_BASE_BYTES + 4*256)

__device__ __forceinline__ float elu1(float x){ return x > 0.f ? x + 1.f : __expf(x); }
__device__ __forceinline__ uint32_t s2u(const void* p){ return (uint32_t)__cvta_generic_to_shared(p); }
__device__ __forceinline__ void barg(int id){ asm volatile("bar.sync %0, 128;" :: "r"(id) : "memory"); }
__device__ __forceinline__ uint32_t h2u(__half2 h){ return *reinterpret_cast<uint32_t*>(&h); }

__device__ __forceinline__ void ldsm4(uint32_t& r0,uint32_t& r1,uint32_t& r2,uint32_t& r3,uint32_t a){
    asm volatile("ldmatrix.sync.aligned.m8n8.x4.shared.b16 {%0,%1,%2,%3},[%4];"
                 : "=r"(r0),"=r"(r1),"=r"(r2),"=r"(r3) : "r"(a));
}
__device__ __forceinline__ void ldsm4t(uint32_t& r0,uint32_t& r1,uint32_t& r2,uint32_t& r3,uint32_t a){
    asm volatile("ldmatrix.sync.aligned.m8n8.x4.trans.shared.b16 {%0,%1,%2,%3},[%4];"
                 : "=r"(r0),"=r"(r1),"=r"(r2),"=r"(r3) : "r"(a));
}
__device__ __forceinline__ void mma16(float& c0,float& c1,float& c2,float& c3,
                                      uint32_t a0,uint32_t a1,uint32_t a2,uint32_t a3,
                                      uint32_t b0,uint32_t b1){
    asm("mma.sync.aligned.m16n8k16.row.col.f32.f16.f16.f32 "
        "{%0,%1,%2,%3},{%4,%5,%6,%7},{%8,%9},{%0,%1,%2,%3};"
        : "+f"(c0),"+f"(c1),"+f"(c2),"+f"(c3)
        : "r"(a0),"r"(a1),"r"(a2),"r"(a3),"r"(b0),"r"(b1));
}

// LDG fp32 -> elu+1 -> fp16 -> STS ; optional fused new_norm column partials (smem atomics)
__device__ __forceinline__ void stage_tile(const float* __restrict__ g,
                                           __half* __restrict__ dst, int tg,
                                           float* __restrict__ sNrm, bool donorm){
    const int nb = tg >> 4, c4 = (tg & 15) << 2;
    float cs0=0.f, cs1=0.f, cs2=0.f, cs3=0.f;
#pragma unroll
    for (int i = 0; i < 8; i++){
        const int n = nb + (i << 3);
        float4 v = *(const float4*)&g[(n << 6) + c4];
        v.x = elu1(v.x); v.y = elu1(v.y); v.z = elu1(v.z); v.w = elu1(v.w);
        if (donorm){ cs0 += v.x; cs1 += v.y; cs2 += v.z; cs3 += v.w; }
        uint2 u;
        u.x = h2u(__floats2half2_rn(v.x, v.y));
        u.y = h2u(__floats2half2_rn(v.z, v.w));
        *(uint2*)&dst[n*SH + c4] = u;
    }
    if (donorm){
        atomicAdd(&sNrm[c4],   cs0);
        atomicAdd(&sNrm[c4+1], cs1);
        atomicAdd(&sNrm[c4+2], cs2);
        atomicAdd(&sNrm[c4+3], cs3);
    }
}

// reciprocal denominators for 64 fp16 rows (dot with fp32 sN)
__device__ __forceinline__ void denomh(const __half* __restrict__ sX,
                                       const float* __restrict__ sN,
                                       float* __restrict__ sI, int tg){
    const int row = tg >> 1, hf = tg & 1;
    const uint4* base = (const uint4*)(sX + row*SH + hf*32);
    const float* nb = sN + hf*32;
    float s0 = 0.f;
#pragma unroll
    for (int j = 0; j < 4; j++){
        uint4 u = base[j];
        float2 f0 = __half22float2(*reinterpret_cast<__half2*>(&u.x));
        float2 f1 = __half22float2(*reinterpret_cast<__half2*>(&u.y));
        float2 f2 = __half22float2(*reinterpret_cast<__half2*>(&u.z));
        float2 f3 = __half22float2(*reinterpret_cast<__half2*>(&u.w));
        const float* nn = nb + 8*j;
        s0 = fmaf(f0.x, nn[0], s0); s0 = fmaf(f0.y, nn[1], s0);
        s0 = fmaf(f1.x, nn[2], s0); s0 = fmaf(f1.y, nn[3], s0);
        s0 = fmaf(f2.x, nn[4], s0); s0 = fmaf(f2.y, nn[5], s0);
        s0 = fmaf(f3.x, nn[6], s0); s0 = fmaf(f3.y, nn[7], s0);
    }
    s0 += __shfl_xor_sync(0xffffffffu, s0, 1);
    if (hf == 0) sI[row] = 1.f / fmaxf(s0, EPSV);
}

__global__ void init_tail(const float* __restrict__ pkv,
                          const float* __restrict__ pnorm,
                          float* __restrict__ dout){
    int i = blockIdx.x * 256 + threadIdx.x;
    if (i < KV_SIZE) dout[KV_OFF + i]   = pkv[i];
    if (i < 64*64)   dout[NORM_OFF + i] = pnorm[i];
}

__global__ void __launch_bounds__(256, 2) fw_kernel(
    const float* __restrict__ keys, const float* __restrict__ values,
    const float* __restrict__ queries, const float* __restrict__ outin,
    const float* __restrict__ pkv, const float* __restrict__ pnorm,
    const float* __restrict__ gates, float* __restrict__ dout)
{
    extern __shared__ __align__(16) char smraw[];
    __half* smh = (__half*)smraw;
    float*  smf = (float*)(smraw + F_BASE_BYTES);
    float* sN   = smf;
    float* sNrm = smf + 192;

    const int tid = threadIdx.x;
    const int g   = tid >> 7, tg = tid & 127;
    const int lane = tid & 31;
    const int wg  = (tid >> 5) & 3;
    const int gid = lane >> 2, tig = lane & 3;
    const int n0  = wg << 4;
    const int bh  = blockIdx.y;
    const size_t gOff = (size_t)bh * (8192*64);
    const int rowBase = blockIdx.x*256 + (g << 7);
    const int bid = 1 + g;

    __half* sKV = smh + H_KV;
    __half* sK  = smh + (g ? H_K1 : H_K0);
    __half* sV  = smh + (g ? H_V1 : H_V0);
    float*  sI  = smf + (g ? 128 : 64);

    // ldmatrix lane geometry
    const int ar  = (((lane>>3)&1) << 3) + (lane & 7);  // A(non-trans) rows / B(trans) rows
    const int ac  = (lane >> 4) << 3;                   // matching col offset
    const int ar2 = ((lane >> 4) << 3) + (lane & 7);    // GEMM2 A(trans) rows
    const int ac2 = ((lane >> 3) & 1) << 3;

    const uint32_t aK  = s2u(&sK[(n0 + ar)*SH + ac]);   // GEMM1 A (k rows)
    const uint32_t bKV = s2u(&sKV[ar*SH + ac]);         // GEMM1/3 B (past_kv)
    const uint32_t aK2 = s2u(&sK[ar2*SH + n0 + ac2]);   // GEMM2 A (k^T)
    const uint32_t bV  = s2u(&sV[ar*SH + ac]);          // GEMM2 B (v)
    const uint32_t aQ  = s2u(&sV[(n0 + ar)*SH + ac]);   // GEMM3 A (q in sV)

    // ---- prologue: past_kv -> fp16 smem; norm; zero sNrm ----
#pragma unroll
    for (int i = 0; i < 4; i++){
        int f = tid + (i << 8);
        int n = f >> 4, c4 = (f & 15) << 2;
        float4 v = *(const float4*)&pkv[(size_t)bh*4096 + (n << 6) + c4];
        uint2 u;
        u.x = h2u(__floats2half2_rn(v.x, v.y));
        u.y = h2u(__floats2half2_rn(v.z, v.w));
        *(uint2*)&sKV[n*SH + c4] = u;
    }
    if (tid < 64){ sN[tid] = pnorm[bh*64 + tid]; sNrm[tid] = 0.f; }
    __syncthreads();

    const float et  = __expf(-gates[bh & 15]);
    const float gte = 1.f/(1.f+et), omg = et/(1.f+et);

    float acc[8][4];
#pragma unroll
    for (int a = 0; a < 8; a++){ acc[a][0]=0.f; acc[a][1]=0.f; acc[a][2]=0.f; acc[a][3]=0.f; }

    stage_tile(keys + gOff + (size_t)rowBase*64, sK, tg, sNrm, true);
    barg(bid);

    for (int ch = 0; ch < 2; ++ch){
        const int row0 = rowBase + (ch << 6);

        denomh(sK, sN, sI, tg);
        barg(bid);

        // ---- GEMM1 (two 32-col passes) + fused v-update, values prefetched ----
        const float i1 = sI[n0+gid], i2 = sI[n0+gid+8];
        const size_t vr1 = gOff + (size_t)(row0+n0+gid)*64;
        const size_t vr2 = vr1 + 512;
#pragma unroll
        for (int pass = 0; pass < 2; pass++){
            float2 va[4], vb[4];
#pragma unroll
            for (int nt = 0; nt < 4; nt++){
                const int cc = (pass<<5) + (nt<<3) + (tig<<1);
                va[nt] = *(const float2*)&values[vr1 + cc];
                vb[nt] = *(const float2*)&values[vr2 + cc];
            }
            float c[4][4];
#pragma unroll
            for (int nt = 0; nt < 4; nt++){ c[nt][0]=0.f; c[nt][1]=0.f; c[nt][2]=0.f; c[nt][3]=0.f; }
#pragma unroll
            for (int ks = 0; ks < 4; ks++){
                const int k0 = ks << 4;
                uint32_t a0,a1,a2,a3;
                ldsm4(a0,a1,a2,a3, aK + (k0 << 1));
#pragma unroll
                for (int ntp = 0; ntp < 2; ntp++){
                    uint32_t b0,b1,b2,b3;
                    ldsm4t(b0,b1,b2,b3, bKV + ((k0*SH + (pass<<5) + (ntp<<4)) << 1));
                    mma16(c[2*ntp][0],c[2*ntp][1],c[2*ntp][2],c[2*ntp][3],
                          a0,a1,a2,a3, b0,b1);
                    mma16(c[2*ntp+1][0],c[2*ntp+1][1],c[2*ntp+1][2],c[2*ntp+1][3],
                          a0,a1,a2,a3, b2,b3);
                }
            }
#pragma unroll
            for (int nt = 0; nt < 4; nt++){
                const int cc = (pass<<5) + (nt<<3) + (tig<<1);
                __half2 h1 = __floats2half2_rn(va[nt].x - c[nt][0]*i1,
                                               va[nt].y - c[nt][1]*i1);
                __half2 h2 = __floats2half2_rn(vb[nt].x - c[nt][2]*i2,
                                               vb[nt].y - c[nt][3]*i2);
                *(uint32_t*)&sV[(n0+gid)*SH + cc]   = h2u(h1);
                *(uint32_t*)&sV[(n0+gid+8)*SH + cc] = h2u(h2);
            }
        }
        barg(bid);

        // ---- GEMM2: acc += k^T v ----
#pragma unroll
        for (int ks = 0; ks < 4; ks++){
            const int k0 = ks << 4;
            uint32_t a0,a1,a2,a3;
            ldsm4t(a0,a1,a2,a3, aK2 + ((k0*SH) << 1));
#pragma unroll
            for (int ntp = 0; ntp < 4; ntp++){
                uint32_t b0,b1,b2,b3;
                ldsm4t(b0,b1,b2,b3, bV + ((k0*SH + (ntp<<4)) << 1));
                mma16(acc[2*ntp][0],acc[2*ntp][1],acc[2*ntp][2],acc[2*ntp][3],
                      a0,a1,a2,a3, b0,b1);
                mma16(acc[2*ntp+1][0],acc[2*ntp+1][1],acc[2*ntp+1][2],acc[2*ntp+1][3],
                      a0,a1,a2,a3, b2,b3);
            }
        }
        barg(bid);

        // ---- stage next k, stage q (sV free after GEMM2) ----
        if (ch == 0)
            stage_tile(keys + gOff + (size_t)(row0+64)*64, sK, tg, sNrm, true);
        stage_tile(queries + gOff + (size_t)row0*64, sV, tg, sNrm, false);
        barg(bid);

        denomh(sV, sN, sI, tg);
        barg(bid);

        // ---- GEMM3 (two passes) + fused gated epilogue, outin prefetched ----
        const float s1 = sI[n0+gid]*omg, s2 = sI[n0+gid+8]*omg;
        const size_t r1 = gOff + (size_t)(row0+n0+gid)*64;
        const size_t r2 = r1 + 512;
#pragma unroll
        for (int pass = 0; pass < 2; pass++){
            float2 oa[4], ob[4];
#pragma unroll
            for (int nt = 0; nt < 4; nt++){
                const int cc = (pass<<5) + (nt<<3) + (tig<<1);
                oa[nt] = *(const float2*)&outin[r1 + cc];
                ob[nt] = *(const float2*)&outin[r2 + cc];
            }
            float c[4][4];
#pragma unroll
            for (int nt = 0; nt < 4; nt++){ c[nt][0]=0.f; c[nt][1]=0.f; c[nt][2]=0.f; c[nt][3]=0.f; }
#pragma unroll
            for (int ks = 0; ks < 4; ks++){
                const int k0 = ks << 4;
                uint32_t a0,a1,a2,a3;
                ldsm4(a0,a1,a2,a3, aQ + (k0 << 1));
#pragma unroll
                for (int ntp = 0; ntp < 2; ntp++){
                    uint32_t b0,b1,b2,b3;
                    ldsm4t(b0,b1,b2,b3, bKV + ((k0*SH + (pass<<5) + (ntp<<4)) << 1));
                    mma16(c[2*ntp][0],c[2*ntp][1],c[2*ntp][2],c[2*ntp][3],
                          a0,a1,a2,a3, b0,b1);
                    mma16(c[2*ntp+1][0],c[2*ntp+1][1],c[2*ntp+1][2],c[2*ntp+1][3],
                          a0,a1,a2,a3, b2,b3);
                }
            }
#pragma unroll
            for (int nt = 0; nt < 4; nt++){
                const int cc = (pass<<5) + (nt<<3) + (tig<<1);
                float2 o1 = oa[nt], o2 = ob[nt];
                o1.x = o1.x*gte + c[nt][0]*s1; o1.y = o1.y*gte + c[nt][1]*s1;
                o2.x = o2.x*gte + c[nt][2]*s2; o2.y = o2.y*gte + c[nt][3]*s2;
                *(float2*)&dout[r1 + cc] = o1;
                *(float2*)&dout[r2 + cc] = o2;
            }
        }
        barg(bid);
    }

    // ---- combine group partials in smem, single atomic flush ----
    __syncthreads();
    float* sComb = (float*)(smh + H_K0);      // overlays dead K tiles (18KB >= 16KB)
    const int m0 = n0;
    if (g == 0){
#pragma unroll
        for (int j = 0; j < 8; j++){
            const int cc = (j<<3) + (tig<<1);
            sComb[(m0+gid)*64   + cc]     = acc[j][0];
            sComb[(m0+gid)*64   + cc + 1] = acc[j][1];
            sComb[(m0+gid+8)*64 + cc]     = acc[j][2];
            sComb[(m0+gid+8)*64 + cc + 1] = acc[j][3];
        }
    }
    __syncthreads();
    if (g == 1){
#pragma unroll
        for (int j = 0; j < 8; j++){
            const int cc = (j<<3) + (tig<<1);
            sComb[(m0+gid)*64   + cc]     += acc[j][0];
            sComb[(m0+gid)*64   + cc + 1] += acc[j][1];
            sComb[(m0+gid+8)*64 + cc]     += acc[j][2];
            sComb[(m0+gid+8)*64 + cc + 1] += acc[j][3];
        }
    }
    __syncthreads();
    float* kvout = dout + KV_OFF + bh * 4096;
#pragma unroll
    for (int k = 0; k < 16; k++){
        const int idx = tid + (k << 8);
        atomicAdd(&kvout[idx], sComb[idx]);
    }
    if (tid < 64) atomicAdd(&dout[NORM_OFF + bh*64 + tid], sNrm[tid]);
}

extern "C" void kernel_launch(void* const* d_in, const int* in_sizes, int n_in,
                              void* d_out, int out_size)
{
    const float* keys    = (const float*)d_in[0];
    const float* values  = (const float*)d_in[1];
    const float* queries = (const float*)d_in[2];
    const float* outin   = (const float*)d_in[3];
    const float* pkv     = (const float*)d_in[4];
    const float* pnorm   = (const float*)d_in[5];
    const float* gates   = (const float*)d_in[6];
    float* dout = (float*)d_out;

    cudaFuncSetAttribute(fw_kernel, cudaFuncAttributeMaxDynamicSharedMemorySize, SMEM_BYTES);

    init_tail<<<1024, 256>>>(pkv, pnorm, dout);
    fw_kernel<<<dim3(32, 64), 256, SMEM_BYTES>>>(keys, values, queries, outin,
                                                 pkv, pnorm, gates, dout);
}

// round 6
// speedup vs baseline: 2.9470x; 1.1766x over previous
#include <cuda_runtime.h>
#include <cuda_fp16.h>
#include <cstdint>

#define KV_OFF   (64*8192*64)
#define KV_SIZE  (64*64*64)
#define NORM_OFF (KV_OFF + KV_SIZE)
#define EPSV 1e-10f
#define SH 72                     // halves per fp16 tile row (144B)
#define SF 68                     // floats per fp32 staging row

// half-unit offsets
#define H_KV 0
#define H_K0 4608
#define H_K1 9216
#define H_V0 13824
#define H_V1 18432
#define STG_BYTES0 46080          // group0 staging (64*SF floats = 17408B)
#define STG_BYTES1 63488
#define F_BASE_BYTES 80896        // sN[64], sI0[64], sI1[64], sNrm[64]
#define SMEM_BYTES (F_BASE_BYTES + 1024)

__device__ __forceinline__ float elu1(float x){ return x > 0.f ? x + 1.f : __expf(x); }
__device__ __forceinline__ uint32_t s2u(const void* p){ return (uint32_t)__cvta_generic_to_shared(p); }
__device__ __forceinline__ void barg(int id){ asm volatile("bar.sync %0, 128;" :: "r"(id) : "memory"); }
__device__ __forceinline__ uint32_t h2u(__half2 h){ return *reinterpret_cast<uint32_t*>(&h); }
__device__ __forceinline__ void cpa16(uint32_t s, const void* g){
    asm volatile("cp.async.cg.shared.global [%0], [%1], 16;" :: "r"(s), "l"(g));
}
#define CP_COMMIT() asm volatile("cp.async.commit_group;")
#define CP_WAIT0()  asm volatile("cp.async.wait_group 0;")

__device__ __forceinline__ void ldsm4(uint32_t& r0,uint32_t& r1,uint32_t& r2,uint32_t& r3,uint32_t a){
    asm volatile("ldmatrix.sync.aligned.m8n8.x4.shared.b16 {%0,%1,%2,%3},[%4];"
                 : "=r"(r0),"=r"(r1),"=r"(r2),"=r"(r3) : "r"(a));
}
__device__ __forceinline__ void ldsm4t(uint32_t& r0,uint32_t& r1,uint32_t& r2,uint32_t& r3,uint32_t a){
    asm volatile("ldmatrix.sync.aligned.m8n8.x4.trans.shared.b16 {%0,%1,%2,%3},[%4];"
                 : "=r"(r0),"=r"(r1),"=r"(r2),"=r"(r3) : "r"(a));
}
__device__ __forceinline__ void mma16(float& c0,float& c1,float& c2,float& c3,
                                      uint32_t a0,uint32_t a1,uint32_t a2,uint32_t a3,
                                      uint32_t b0,uint32_t b1){
    asm("mma.sync.aligned.m16n8k16.row.col.f32.f16.f16.f32 "
        "{%0,%1,%2,%3},{%4,%5,%6,%7},{%8,%9},{%0,%1,%2,%3};"
        : "+f"(c0),"+f"(c1),"+f"(c2),"+f"(c3)
        : "r"(a0),"r"(a1),"r"(a2),"r"(a3),"r"(b0),"r"(b1));
}

// issue cp.async fill of one 64x64 fp32 tile into this group's staging buffer
__device__ __forceinline__ void cp_fill(const float* __restrict__ g,
                                        float* __restrict__ stg, int tg){
#pragma unroll
    for (int i = 0; i < 8; i++){
        int f = tg + (i << 7);
        int n = f >> 4, c4 = (f & 15) << 2;
        cpa16(s2u(&stg[n*SF + c4]), &g[(n << 6) + c4]);
    }
    CP_COMMIT();
}

// staging fp32 -> elu+1 -> fp16 tile; optional fused new_norm column partials.
// Same per-thread chunks as cp_fill => own cp.async wait suffices, no barrier.
__device__ __forceinline__ void cvt_from_stage(const float* __restrict__ stg,
                                               __half* __restrict__ dst, int tg,
                                               float* __restrict__ sNrm, bool donorm){
    const int nb = tg >> 4, c4 = (tg & 15) << 2;
    float cs0=0.f, cs1=0.f, cs2=0.f, cs3=0.f;
#pragma unroll
    for (int i = 0; i < 8; i++){
        const int n = (nb << 3) + i;          // 8 consecutive rows per thread-col
        float4 v = *(const float4*)&stg[n*SF + c4];
        v.x = elu1(v.x); v.y = elu1(v.y); v.z = elu1(v.z); v.w = elu1(v.w);
        if (donorm){ cs0 += v.x; cs1 += v.y; cs2 += v.z; cs3 += v.w; }
        uint2 u;
        u.x = h2u(__floats2half2_rn(v.x, v.y));
        u.y = h2u(__floats2half2_rn(v.z, v.w));
        *(uint2*)&dst[n*SH + c4] = u;
    }
    if (donorm){
        atomicAdd(&sNrm[c4],   cs0);
        atomicAdd(&sNrm[c4+1], cs1);
        atomicAdd(&sNrm[c4+2], cs2);
        atomicAdd(&sNrm[c4+3], cs3);
    }
}

// reciprocal denominators for 64 fp16 rows (dot with fp32 sN)
__device__ __forceinline__ void denomh(const __half* __restrict__ sX,
                                       const float* __restrict__ sN,
                                       float* __restrict__ sI, int tg){
    const int row = tg >> 1, hf = tg & 1;
    const uint4* base = (const uint4*)(sX + row*SH + hf*32);
    const float* nb = sN + hf*32;
    float s0 = 0.f;
#pragma unroll
    for (int j = 0; j < 4; j++){
        uint4 u = base[j];
        float2 f0 = __half22float2(*reinterpret_cast<__half2*>(&u.x));
        float2 f1 = __half22float2(*reinterpret_cast<__half2*>(&u.y));
        float2 f2 = __half22float2(*reinterpret_cast<__half2*>(&u.z));
        float2 f3 = __half22float2(*reinterpret_cast<__half2*>(&u.w));
        const float* nn = nb + 8*j;
        s0 = fmaf(f0.x, nn[0], s0); s0 = fmaf(f0.y, nn[1], s0);
        s0 = fmaf(f1.x, nn[2], s0); s0 = fmaf(f1.y, nn[3], s0);
        s0 = fmaf(f2.x, nn[4], s0); s0 = fmaf(f2.y, nn[5], s0);
        s0 = fmaf(f3.x, nn[6], s0); s0 = fmaf(f3.y, nn[7], s0);
    }
    s0 += __shfl_xor_sync(0xffffffffu, s0, 1);
    if (hf == 0) sI[row] = 1.f / fmaxf(s0, EPSV);
}

__global__ void init_tail(const float* __restrict__ pkv,
                          const float* __restrict__ pnorm,
                          float* __restrict__ dout){
    int i = blockIdx.x * 256 + threadIdx.x;
    if (i < KV_SIZE) dout[KV_OFF + i]   = pkv[i];
    if (i < 64*64)   dout[NORM_OFF + i] = pnorm[i];
}

__global__ void __launch_bounds__(256, 2) fw_kernel(
    const float* __restrict__ keys, const float* __restrict__ values,
    const float* __restrict__ queries, const float* __restrict__ outin,
    const float* __restrict__ pkv, const float* __restrict__ pnorm,
    const float* __restrict__ gates, float* __restrict__ dout)
{
    extern __shared__ __align__(16) char smraw[];
    __half* smh = (__half*)smraw;
    float*  smf = (float*)(smraw + F_BASE_BYTES);
    float* sN   = smf;
    float* sNrm = smf + 192;

    const int tid = threadIdx.x;
    const int g   = tid >> 7, tg = tid & 127;
    const int lane = tid & 31;
    const int wg  = (tid >> 5) & 3;
    const int gid = lane >> 2, tig = lane & 3;
    const int n0  = wg << 4;
    const int bh  = blockIdx.y;
    const size_t gOff = (size_t)bh * (8192*64);
    const int rowBase = blockIdx.x*256 + (g << 7);
    const int bid = 1 + g;

    __half* sKV = smh + H_KV;
    __half* sK  = smh + (g ? H_K1 : H_K0);
    __half* sV  = smh + (g ? H_V1 : H_V0);
    float*  stg = (float*)(smraw + (g ? STG_BYTES1 : STG_BYTES0));
    float*  sI  = smf + (g ? 128 : 64);

    // ldmatrix lane geometry
    const int ar  = (((lane>>3)&1) << 3) + (lane & 7);
    const int ac  = (lane >> 4) << 3;
    const int ar2 = ((lane >> 4) << 3) + (lane & 7);
    const int ac2 = ((lane >> 3) & 1) << 3;

    const uint32_t aK  = s2u(&sK[(n0 + ar)*SH + ac]);
    const uint32_t bKV = s2u(&sKV[ar*SH + ac]);
    const uint32_t aK2 = s2u(&sK[ar2*SH + n0 + ac2]);
    const uint32_t bV  = s2u(&sV[ar*SH + ac]);
    const uint32_t aQ  = s2u(&sV[(n0 + ar)*SH + ac]);

    // ---- prologue: k(ch0) via cp.async; past_kv via LDG (one-time) ----
    cp_fill(keys + gOff + (size_t)rowBase*64, stg, tg);
#pragma unroll
    for (int i = 0; i < 4; i++){
        int f = tid + (i << 8);
        int n = f >> 4, c4 = (f & 15) << 2;
        float4 v = *(const float4*)&pkv[(size_t)bh*4096 + (n << 6) + c4];
        uint2 u;
        u.x = h2u(__floats2half2_rn(v.x, v.y));
        u.y = h2u(__floats2half2_rn(v.z, v.w));
        *(uint2*)&sKV[n*SH + c4] = u;
    }
    if (tid < 64){ sN[tid] = pnorm[bh*64 + tid]; sNrm[tid] = 0.f; }
    __syncthreads();

    const float et  = __expf(-gates[bh & 15]);
    const float gte = 1.f/(1.f+et), omg = et/(1.f+et);

    float acc[8][4];
#pragma unroll
    for (int a = 0; a < 8; a++){ acc[a][0]=0.f; acc[a][1]=0.f; acc[a][2]=0.f; acc[a][3]=0.f; }

    for (int ch = 0; ch < 2; ++ch){
        const int row0 = rowBase + (ch << 6);

        // ---- consume staged k; immediately refill staging with q(ch) ----
        CP_WAIT0();
        cvt_from_stage(stg, sK, tg, sNrm, true);
        cp_fill(queries + gOff + (size_t)row0*64, stg, tg);
        barg(bid);
        denomh(sK, sN, sI, tg);
        barg(bid);

        // ---- GEMM1 (two 32-col passes) + fused v-update, values reg-prefetch ----
        const float i1 = sI[n0+gid], i2 = sI[n0+gid+8];
        const size_t vr1 = gOff + (size_t)(row0+n0+gid)*64;
        const size_t vr2 = vr1 + 512;
#pragma unroll
        for (int pass = 0; pass < 2; pass++){
            float2 va[4], vb[4];
#pragma unroll
            for (int nt = 0; nt < 4; nt++){
                const int cc = (pass<<5) + (nt<<3) + (tig<<1);
                va[nt] = *(const float2*)&values[vr1 + cc];
                vb[nt] = *(const float2*)&values[vr2 + cc];
            }
            float c[4][4];
#pragma unroll
            for (int nt = 0; nt < 4; nt++){ c[nt][0]=0.f; c[nt][1]=0.f; c[nt][2]=0.f; c[nt][3]=0.f; }
#pragma unroll
            for (int ks = 0; ks < 4; ks++){
                const int k0 = ks << 4;
                uint32_t a0,a1,a2,a3;
                ldsm4(a0,a1,a2,a3, aK + (k0 << 1));
#pragma unroll
                for (int ntp = 0; ntp < 2; ntp++){
                    uint32_t b0,b1,b2,b3;
                    ldsm4t(b0,b1,b2,b3, bKV + ((k0*SH + (pass<<5) + (ntp<<4)) << 1));
                    mma16(c[2*ntp][0],c[2*ntp][1],c[2*ntp][2],c[2*ntp][3],
                          a0,a1,a2,a3, b0,b1);
                    mma16(c[2*ntp+1][0],c[2*ntp+1][1],c[2*ntp+1][2],c[2*ntp+1][3],
                          a0,a1,a2,a3, b2,b3);
                }
            }
#pragma unroll
            for (int nt = 0; nt < 4; nt++){
                const int cc = (pass<<5) + (nt<<3) + (tig<<1);
                __half2 h1 = __floats2half2_rn(va[nt].x - c[nt][0]*i1,
                                               va[nt].y - c[nt][1]*i1);
                __half2 h2 = __floats2half2_rn(vb[nt].x - c[nt][2]*i2,
                                               vb[nt].y - c[nt][3]*i2);
                *(uint32_t*)&sV[(n0+gid)*SH + cc]   = h2u(h1);
                *(uint32_t*)&sV[(n0+gid+8)*SH + cc] = h2u(h2);
            }
        }
        barg(bid);

        // ---- GEMM2: acc += k^T v ----
#pragma unroll
        for (int ks = 0; ks < 4; ks++){
            const int k0 = ks << 4;
            uint32_t a0,a1,a2,a3;
            ldsm4t(a0,a1,a2,a3, aK2 + ((k0*SH) << 1));
#pragma unroll
            for (int ntp = 0; ntp < 4; ntp++){
                uint32_t b0,b1,b2,b3;
                ldsm4t(b0,b1,b2,b3, bV + ((k0*SH + (ntp<<4)) << 1));
                mma16(acc[2*ntp][0],acc[2*ntp][1],acc[2*ntp][2],acc[2*ntp][3],
                      a0,a1,a2,a3, b0,b1);
                mma16(acc[2*ntp+1][0],acc[2*ntp+1][1],acc[2*ntp+1][2],acc[2*ntp+1][3],
                      a0,a1,a2,a3, b2,b3);
            }
        }
        barg(bid);

        // ---- consume staged q into sV (free after GEMM2); refill with k(ch+1) ----
        CP_WAIT0();
        cvt_from_stage(stg, sV, tg, sNrm, false);
        if (ch == 0)
            cp_fill(keys + gOff + (size_t)(row0+64)*64, stg, tg);
        barg(bid);
        denomh(sV, sN, sI, tg);
        barg(bid);

        // ---- GEMM3 (two passes) + fused gated epilogue, outin reg-prefetch ----
        const float s1 = sI[n0+gid]*omg, s2 = sI[n0+gid+8]*omg;
        const size_t r1 = gOff + (size_t)(row0+n0+gid)*64;
        const size_t r2 = r1 + 512;
#pragma unroll
        for (int pass = 0; pass < 2; pass++){
            float2 oa[4], ob[4];
#pragma unroll
            for (int nt = 0; nt < 4; nt++){
                const int cc = (pass<<5) + (nt<<3) + (tig<<1);
                oa[nt] = *(const float2*)&outin[r1 + cc];
                ob[nt] = *(const float2*)&outin[r2 + cc];
            }
            float c[4][4];
#pragma unroll
            for (int nt = 0; nt < 4; nt++){ c[nt][0]=0.f; c[nt][1]=0.f; c[nt][2]=0.f; c[nt][3]=0.f; }
#pragma unroll
            for (int ks = 0; ks < 4; ks++){
                const int k0 = ks << 4;
                uint32_t a0,a1,a2,a3;
                ldsm4(a0,a1,a2,a3, aQ + (k0 << 1));
#pragma unroll
                for (int ntp = 0; ntp < 2; ntp++){
                    uint32_t b0,b1,b2,b3;
                    ldsm4t(b0,b1,b2,b3, bKV + ((k0*SH + (pass<<5) + (ntp<<4)) << 1));
                    mma16(c[2*ntp][0],c[2*ntp][1],c[2*ntp][2],c[2*ntp][3],
                          a0,a1,a2,a3, b0,b1);
                    mma16(c[2*ntp+1][0],c[2*ntp+1][1],c[2*ntp+1][2],c[2*ntp+1][3],
                          a0,a1,a2,a3, b2,b3);
                }
            }
#pragma unroll
            for (int nt = 0; nt < 4; nt++){
                const int cc = (pass<<5) + (nt<<3) + (tig<<1);
                float2 o1 = oa[nt], o2 = ob[nt];
                o1.x = o1.x*gte + c[nt][0]*s1; o1.y = o1.y*gte + c[nt][1]*s1;
                o2.x = o2.x*gte + c[nt][2]*s2; o2.y = o2.y*gte + c[nt][3]*s2;
                *(float2*)&dout[r1 + cc] = o1;
                *(float2*)&dout[r2 + cc] = o2;
            }
        }
        barg(bid);
    }

    // ---- combine group partials in smem, single atomic flush ----
    __syncthreads();
    float* sComb = (float*)(smh + H_K0);
    const int m0 = n0;
    if (g == 0){
#pragma unroll
        for (int j = 0; j < 8; j++){
            const int cc = (j<<3) + (tig<<1);
            sComb[(m0+gid)*64   + cc]     = acc[j][0];
            sComb[(m0+gid)*64   + cc + 1] = acc[j][1];
            sComb[(m0+gid+8)*64 + cc]     = acc[j][2];
            sComb[(m0+gid+8)*64 + cc + 1] = acc[j][3];
        }
    }
    __syncthreads();
    if (g == 1){
#pragma unroll
        for (int j = 0; j < 8; j++){
            const int cc = (j<<3) + (tig<<1);
            sComb[(m0+gid)*64   + cc]     += acc[j][0];
            sComb[(m0+gid)*64   + cc + 1] += acc[j][1];
            sComb[(m0+gid+8)*64 + cc]     += acc[j][2];
            sComb[(m0+gid+8)*64 + cc + 1] += acc[j][3];
        }
    }
    __syncthreads();
    float* kvout = dout + KV_OFF + bh * 4096;
#pragma unroll
    for (int k = 0; k < 16; k++){
        const int idx = tid + (k << 8);
        atomicAdd(&kvout[idx], sComb[idx]);
    }
    if (tid < 64) atomicAdd(&dout[NORM_OFF + bh*64 + tid], sNrm[tid]);
}

extern "C" void kernel_launch(void* const* d_in, const int* in_sizes, int n_in,
                              void* d_out, int out_size)
{
    const float* keys    = (const float*)d_in[0];
    const float* values  = (const float*)d_in[1];
    const float* queries = (const float*)d_in[2];
    const float* outin   = (const float*)d_in[3];
    const float* pkv     = (const float*)d_in[4];
    const float* pnorm   = (const float*)d_in[5];
    const float* gates   = (const float*)d_in[6];
    float* dout = (float*)d_out;

    cudaFuncSetAttribute(fw_kernel, cudaFuncAttributeMaxDynamicSharedMemorySize, SMEM_BYTES);

    init_tail<<<1024, 256>>>(pkv, pnorm, dout);
    fw_kernel<<<dim3(32, 64), 256, SMEM_BYTES>>>(keys, values, queries, outin,
                                                 pkv, pnorm, gates, dout);
}

// round 7
// speedup vs baseline: 2.9615x; 1.0049x over previous
#include <cuda_runtime.h>
#include <cuda_fp16.h>
#include <cstdint>

#define KV_OFF   (64*8192*64)
#define KV_SIZE  (64*64*64)
#define NORM_OFF (KV_OFF + KV_SIZE)
#define EPSV 1e-10f
#define SH 72                     // halves per fp16 tile row (144B)
#define SF 68                     // floats per fp32 staging row

// half-unit offsets
#define H_KV 0
#define H_K0 4608
#define H_K1 9216
#define H_V0 13824
#define H_V1 18432
#define STG_BYTES0 46080          // group0 staging (64*SF floats)
#define STG_BYTES1 63488
#define F_BASE_BYTES 80896        // sN[64], sI0[64], sI1[64], sNrm[64]
#define SMEM_BYTES (F_BASE_BYTES + 1024)

__device__ __forceinline__ float elu1(float x){ return x > 0.f ? x + 1.f : __expf(x); }
__device__ __forceinline__ uint32_t s2u(const void* p){ return (uint32_t)__cvta_generic_to_shared(p); }
__device__ __forceinline__ void barg(int id){ asm volatile("bar.sync %0, 128;" :: "r"(id) : "memory"); }
__device__ __forceinline__ uint32_t h2u(__half2 h){ return *reinterpret_cast<uint32_t*>(&h); }
__device__ __forceinline__ void cpa16(uint32_t s, const void* g){
    asm volatile("cp.async.cg.shared.global [%0], [%1], 16;" :: "r"(s), "l"(g));
}
#define CP_COMMIT() asm volatile("cp.async.commit_group;")
#define CP_WAIT0()  asm volatile("cp.async.wait_group 0;")

__device__ __forceinline__ void ldsm4(uint32_t& r0,uint32_t& r1,uint32_t& r2,uint32_t& r3,uint32_t a){
    asm volatile("ldmatrix.sync.aligned.m8n8.x4.shared.b16 {%0,%1,%2,%3},[%4];"
                 : "=r"(r0),"=r"(r1),"=r"(r2),"=r"(r3) : "r"(a));
}
__device__ __forceinline__ void ldsm4t(uint32_t& r0,uint32_t& r1,uint32_t& r2,uint32_t& r3,uint32_t a){
    asm volatile("ldmatrix.sync.aligned.m8n8.x4.trans.shared.b16 {%0,%1,%2,%3},[%4];"
                 : "=r"(r0),"=r"(r1),"=r"(r2),"=r"(r3) : "r"(a));
}
__device__ __forceinline__ void mma16(float& c0,float& c1,float& c2,float& c3,
                                      uint32_t a0,uint32_t a1,uint32_t a2,uint32_t a3,
                                      uint32_t b0,uint32_t b1){
    asm("mma.sync.aligned.m16n8k16.row.col.f32.f16.f16.f32 "
        "{%0,%1,%2,%3},{%4,%5,%6,%7},{%8,%9},{%0,%1,%2,%3};"
        : "+f"(c0),"+f"(c1),"+f"(c2),"+f"(c3)
        : "r"(a0),"r"(a1),"r"(a2),"r"(a3),"r"(b0),"r"(b1));
}

// issue cp.async fill of one 64x64 fp32 tile; thread writes rows nb+8i
__device__ __forceinline__ void cp_fill(const float* __restrict__ g,
                                        float* __restrict__ stg, int tg){
#pragma unroll
    for (int i = 0; i < 8; i++){
        int f = tg + (i << 7);
        int n = f >> 4, c4 = (f & 15) << 2;
        cpa16(s2u(&stg[n*SF + c4]), &g[(n << 6) + c4]);
    }
    CP_COMMIT();
}

// staging fp32 -> elu+1 -> fp16 tile, fused row-dot denominators (via 16-lane
// butterfly) and optional new_norm column partial accumulation in registers.
// Reads EXACTLY the rows this thread cp.async'd (n = nb + 8i): wait_group-only
// visibility is same-thread, so this is memory-model-safe with no barrier.
__device__ __forceinline__ void cvt_denom(const float* __restrict__ stg,
                                          __half* __restrict__ dst, int tg, int lane,
                                          float n0f, float n1f, float n2f, float n3f,
                                          float* __restrict__ sI,
                                          bool donorm, float (&nrm)[4]){
    const int nb = tg >> 4, c4 = (tg & 15) << 2;
    float rp[8];
#pragma unroll
    for (int i = 0; i < 8; i++){
        const int n = nb + (i << 3);
        float4 v = *(const float4*)&stg[n*SF + c4];
        v.x = elu1(v.x); v.y = elu1(v.y); v.z = elu1(v.z); v.w = elu1(v.w);
        if (donorm){ nrm[0] += v.x; nrm[1] += v.y; nrm[2] += v.z; nrm[3] += v.w; }
        float t = v.x * n0f;
        t = fmaf(v.y, n1f, t); t = fmaf(v.z, n2f, t); t = fmaf(v.w, n3f, t);
        rp[i] = t;
        uint2 u;
        u.x = h2u(__floats2half2_rn(v.x, v.y));
        u.y = h2u(__floats2half2_rn(v.z, v.w));
        *(uint2*)&dst[n*SH + c4] = u;
    }
#pragma unroll
    for (int m = 1; m < 16; m <<= 1)
#pragma unroll
        for (int i = 0; i < 8; i++)
            rp[i] += __shfl_xor_sync(0xffffffffu, rp[i], m);
    if ((lane & 15) == 0)
#pragma unroll
        for (int i = 0; i < 8; i++)
            sI[nb + (i << 3)] = 1.f / fmaxf(rp[i], EPSV);
}

__global__ void init_tail(const float* __restrict__ pkv,
                          const float* __restrict__ pnorm,
                          float* __restrict__ dout){
    int i = blockIdx.x * 256 + threadIdx.x;
    if (i < KV_SIZE) dout[KV_OFF + i]   = pkv[i];
    if (i < 64*64)   dout[NORM_OFF + i] = pnorm[i];
}

__global__ void __launch_bounds__(256, 2) fw_kernel(
    const float* __restrict__ keys, const float* __restrict__ values,
    const float* __restrict__ queries, const float* __restrict__ outin,
    const float* __restrict__ pkv, const float* __restrict__ pnorm,
    const float* __restrict__ gates, float* __restrict__ dout)
{
    extern __shared__ __align__(16) char smraw[];
    __half* smh = (__half*)smraw;
    float*  smf = (float*)(smraw + F_BASE_BYTES);
    float* sN   = smf;
    float* sNrm = smf + 192;

    const int tid = threadIdx.x;
    const int g   = tid >> 7, tg = tid & 127;
    const int lane = tid & 31;
    const int wg  = (tid >> 5) & 3;
    const int gid = lane >> 2, tig = lane & 3;
    const int n0  = wg << 4;
    const int bh  = blockIdx.y;
    const size_t gOff = (size_t)bh * (8192*64);
    const int rowBase = blockIdx.x*256 + (g << 7);
    const int bid = 1 + g;

    __half* sKV = smh + H_KV;
    __half* sK  = smh + (g ? H_K1 : H_K0);
    __half* sV  = smh + (g ? H_V1 : H_V0);
    float*  stg = (float*)(smraw + (g ? STG_BYTES1 : STG_BYTES0));
    float*  sI  = smf + (g ? 128 : 64);

    // ldmatrix lane geometry
    const int ar  = (((lane>>3)&1) << 3) + (lane & 7);
    const int ac  = (lane >> 4) << 3;
    const int ar2 = ((lane >> 4) << 3) + (lane & 7);
    const int ac2 = ((lane >> 3) & 1) << 3;

    const uint32_t aK  = s2u(&sK[(n0 + ar)*SH + ac]);
    const uint32_t bKV = s2u(&sKV[ar*SH + ac]);
    const uint32_t aK2 = s2u(&sK[ar2*SH + n0 + ac2]);
    const uint32_t bV  = s2u(&sV[ar*SH + ac]);
    const uint32_t aQ  = s2u(&sV[(n0 + ar)*SH + ac]);

    // ---- prologue ----
    cp_fill(keys + gOff + (size_t)rowBase*64, stg, tg);
#pragma unroll
    for (int i = 0; i < 4; i++){
        int f = tid + (i << 8);
        int n = f >> 4, c4 = (f & 15) << 2;
        float4 v = *(const float4*)&pkv[(size_t)bh*4096 + (n << 6) + c4];
        uint2 u;
        u.x = h2u(__floats2half2_rn(v.x, v.y));
        u.y = h2u(__floats2half2_rn(v.z, v.w));
        *(uint2*)&sKV[n*SH + c4] = u;
    }
    if (tid < 64){ sN[tid] = pnorm[bh*64 + tid]; sNrm[tid] = 0.f; }
    __syncthreads();

    const float et  = __expf(-gates[bh & 15]);
    const float gte = 1.f/(1.f+et), omg = et/(1.f+et);
    // per-thread norm weights for fused denominators
    const int c4t = (tg & 15) << 2;
    const float n0f = sN[c4t], n1f = sN[c4t+1], n2f = sN[c4t+2], n3f = sN[c4t+3];

    float acc[8][4];
#pragma unroll
    for (int a = 0; a < 8; a++){ acc[a][0]=0.f; acc[a][1]=0.f; acc[a][2]=0.f; acc[a][3]=0.f; }
    float nrm[4] = {0.f, 0.f, 0.f, 0.f};

    for (int ch = 0; ch < 2; ++ch){
        const int row0 = rowBase + (ch << 6);

        // ---- phase A: consume staged k (fused denom+nrm); refill with q ----
        CP_WAIT0();
        cvt_denom(stg, sK, tg, lane, n0f, n1f, n2f, n3f, sI, true, nrm);
        cp_fill(queries + gOff + (size_t)row0*64, stg, tg);
        barg(bid);

        // ---- phase B: GEMM1 (both passes' values hoisted) + fused v-update ----
        const float i1 = sI[n0+gid], i2 = sI[n0+gid+8];
        const size_t vr1 = gOff + (size_t)(row0+n0+gid)*64;
        const size_t vr2 = vr1 + 512;
        float2 va[8], vb[8];
#pragma unroll
        for (int idx = 0; idx < 8; idx++){
            const int cc = ((idx>>2)<<5) + ((idx&3)<<3) + (tig<<1);
            va[idx] = *(const float2*)&values[vr1 + cc];
            vb[idx] = *(const float2*)&values[vr2 + cc];
        }
#pragma unroll
        for (int pass = 0; pass < 2; pass++){
            float c[4][4];
#pragma unroll
            for (int nt = 0; nt < 4; nt++){ c[nt][0]=0.f; c[nt][1]=0.f; c[nt][2]=0.f; c[nt][3]=0.f; }
#pragma unroll
            for (int ks = 0; ks < 4; ks++){
                const int k0 = ks << 4;
                uint32_t a0,a1,a2,a3;
                ldsm4(a0,a1,a2,a3, aK + (k0 << 1));
#pragma unroll
                for (int ntp = 0; ntp < 2; ntp++){
                    uint32_t b0,b1,b2,b3;
                    ldsm4t(b0,b1,b2,b3, bKV + ((k0*SH + (pass<<5) + (ntp<<4)) << 1));
                    mma16(c[2*ntp][0],c[2*ntp][1],c[2*ntp][2],c[2*ntp][3],
                          a0,a1,a2,a3, b0,b1);
                    mma16(c[2*ntp+1][0],c[2*ntp+1][1],c[2*ntp+1][2],c[2*ntp+1][3],
                          a0,a1,a2,a3, b2,b3);
                }
            }
#pragma unroll
            for (int nt = 0; nt < 4; nt++){
                const int cc = (pass<<5) + (nt<<3) + (tig<<1);
                const int idx = (pass<<2) + nt;
                __half2 h1 = __floats2half2_rn(va[idx].x - c[nt][0]*i1,
                                               va[idx].y - c[nt][1]*i1);
                __half2 h2 = __floats2half2_rn(vb[idx].x - c[nt][2]*i2,
                                               vb[idx].y - c[nt][3]*i2);
                *(uint32_t*)&sV[(n0+gid)*SH + cc]   = h2u(h1);
                *(uint32_t*)&sV[(n0+gid+8)*SH + cc] = h2u(h2);
            }
        }
        barg(bid);

        // ---- phase C: GEMM2 acc += k^T v ----
#pragma unroll
        for (int ks = 0; ks < 4; ks++){
            const int k0 = ks << 4;
            uint32_t a0,a1,a2,a3;
            ldsm4t(a0,a1,a2,a3, aK2 + ((k0*SH) << 1));
#pragma unroll
            for (int ntp = 0; ntp < 4; ntp++){
                uint32_t b0,b1,b2,b3;
                ldsm4t(b0,b1,b2,b3, bV + ((k0*SH + (ntp<<4)) << 1));
                mma16(acc[2*ntp][0],acc[2*ntp][1],acc[2*ntp][2],acc[2*ntp][3],
                      a0,a1,a2,a3, b0,b1);
                mma16(acc[2*ntp+1][0],acc[2*ntp+1][1],acc[2*ntp+1][2],acc[2*ntp+1][3],
                      a0,a1,a2,a3, b2,b3);
            }
        }
        barg(bid);

        // ---- phase D: consume staged q into sV (fused denom); refill k(ch+1) ----
        CP_WAIT0();
        cvt_denom(stg, sV, tg, lane, n0f, n1f, n2f, n3f, sI, false, nrm);
        if (ch == 0)
            cp_fill(keys + gOff + (size_t)(row0+64)*64, stg, tg);
        barg(bid);

        // ---- phase E: GEMM3 + fused gated epilogue ----
        const float s1 = sI[n0+gid]*omg, s2 = sI[n0+gid+8]*omg;
        const size_t r1 = gOff + (size_t)(row0+n0+gid)*64;
        const size_t r2 = r1 + 512;
#pragma unroll
        for (int pass = 0; pass < 2; pass++){
            float2 oa[4], ob[4];
#pragma unroll
            for (int nt = 0; nt < 4; nt++){
                const int cc = (pass<<5) + (nt<<3) + (tig<<1);
                oa[nt] = *(const float2*)&outin[r1 + cc];
                ob[nt] = *(const float2*)&outin[r2 + cc];
            }
            float c[4][4];
#pragma unroll
            for (int nt = 0; nt < 4; nt++){ c[nt][0]=0.f; c[nt][1]=0.f; c[nt][2]=0.f; c[nt][3]=0.f; }
#pragma unroll
            for (int ks = 0; ks < 4; ks++){
                const int k0 = ks << 4;
                uint32_t a0,a1,a2,a3;
                ldsm4(a0,a1,a2,a3, aQ + (k0 << 1));
#pragma unroll
                for (int ntp = 0; ntp < 2; ntp++){
                    uint32_t b0,b1,b2,b3;
                    ldsm4t(b0,b1,b2,b3, bKV + ((k0*SH + (pass<<5) + (ntp<<4)) << 1));
                    mma16(c[2*ntp][0],c[2*ntp][1],c[2*ntp][2],c[2*ntp][3],
                          a0,a1,a2,a3, b0,b1);
                    mma16(c[2*ntp+1][0],c[2*ntp+1][1],c[2*ntp+1][2],c[2*ntp+1][3],
                          a0,a1,a2,a3, b2,b3);
                }
            }
#pragma unroll
            for (int nt = 0; nt < 4; nt++){
                const int cc = (pass<<5) + (nt<<3) + (tig<<1);
                float2 o1 = oa[nt], o2 = ob[nt];
                o1.x = o1.x*gte + c[nt][0]*s1; o1.y = o1.y*gte + c[nt][1]*s1;
                o2.x = o2.x*gte + c[nt][2]*s2; o2.y = o2.y*gte + c[nt][3]*s2;
                *(float2*)&dout[r1 + cc] = o1;
                *(float2*)&dout[r2 + cc] = o2;
            }
        }
        barg(bid);
    }

    // ---- tail: combine partials, flush ----
    __syncthreads();
#pragma unroll
    for (int j = 0; j < 4; j++) atomicAdd(&sNrm[c4t + j], nrm[j]);
    float* sComb = (float*)(smh + H_K0);
    const int m0 = n0;
    if (g == 0){
#pragma unroll
        for (int j = 0; j < 8; j++){
            const int cc = (j<<3) + (tig<<1);
            sComb[(m0+gid)*64   + cc]     = acc[j][0];
            sComb[(m0+gid)*64   + cc + 1] = acc[j][1];
            sComb[(m0+gid+8)*64 + cc]     = acc[j][2];
            sComb[(m0+gid+8)*64 + cc + 1] = acc[j][3];
        }
    }
    __syncthreads();
    if (g == 1){
#pragma unroll
        for (int j = 0; j < 8; j++){
            const int cc = (j<<3) + (tig<<1);
            sComb[(m0+gid)*64   + cc]     += acc[j][0];
            sComb[(m0+gid)*64   + cc + 1] += acc[j][1];
            sComb[(m0+gid+8)*64 + cc]     += acc[j][2];
            sComb[(m0+gid+8)*64 + cc + 1] += acc[j][3];
        }
    }
    __syncthreads();
    float* kvout = dout + KV_OFF + bh * 4096;
#pragma unroll
    for (int k = 0; k < 16; k++){
        const int idx = tid + (k << 8);
        atomicAdd(&kvout[idx], sComb[idx]);
    }
    if (tid < 64) atomicAdd(&dout[NORM_OFF + bh*64 + tid], sNrm[tid]);
}

extern "C" void kernel_launch(void* const* d_in, const int* in_sizes, int n_in,
                              void* d_out, int out_size)
{
    const float* keys    = (const float*)d_in[0];
    const float* values  = (const float*)d_in[1];
    const float* queries = (const float*)d_in[2];
    const float* outin   = (const float*)d_in[3];
    const float* pkv     = (const float*)d_in[4];
    const float* pnorm   = (const float*)d_in[5];
    const float* gates   = (const float*)d_in[6];
    float* dout = (float*)d_out;

    cudaFuncSetAttribute(fw_kernel, cudaFuncAttributeMaxDynamicSharedMemorySize, SMEM_BYTES);

    init_tail<<<1024, 256>>>(pkv, pnorm, dout);
    fw_kernel<<<dim3(32, 64), 256, SMEM_BYTES>>>(keys, values, queries, outin,
                                                 pkv, pnorm, gates, dout);
}

// round 8
// speedup vs baseline: 3.2748x; 1.1058x over previous
#include <cuda_runtime.h>
#include <cuda_fp16.h>
#include <cstdint>

#define KV_OFF   (64*8192*64)
#define KV_SIZE  (64*64*64)
#define NORM_OFF (KV_OFF + KV_SIZE)
#define EPSV 1e-10f
#define SH 72                     // halves per fp16 tile row (144B)
#define SF 68                     // floats per fp32 staging row

// half-unit offsets
#define H_KV 0                    // 64 x SH shared past_kv
#define H_K  4608                 // group0 k tile
#define H_V  9216                 // group0 v tile
#define H_Q  13824                // group1 q tile
#define STG0_BYTES 36864          // group0 staging (64*SF fp32)
#define STG1_BYTES 54272          // group1 staging
#define F_BASE_BYTES 71680        // sN[64], sI0[64], sI1[64], sNrm[64]
#define SMEM_BYTES (F_BASE_BYTES + 1024)

__device__ __forceinline__ float elu1(float x){ return x > 0.f ? x + 1.f : __expf(x); }
__device__ __forceinline__ uint32_t s2u(const void* p){ return (uint32_t)__cvta_generic_to_shared(p); }
__device__ __forceinline__ void barg(int id){ asm volatile("bar.sync %0, 128;" :: "r"(id) : "memory"); }
__device__ __forceinline__ uint32_t h2u(__half2 h){ return *reinterpret_cast<uint32_t*>(&h); }
__device__ __forceinline__ void cpa16(uint32_t s, const void* g){
    asm volatile("cp.async.cg.shared.global [%0], [%1], 16;" :: "r"(s), "l"(g));
}
#define CP_COMMIT() asm volatile("cp.async.commit_group;")
#define CP_WAIT0()  asm volatile("cp.async.wait_group 0;")

__device__ __forceinline__ void ldsm4(uint32_t& r0,uint32_t& r1,uint32_t& r2,uint32_t& r3,uint32_t a){
    asm volatile("ldmatrix.sync.aligned.m8n8.x4.shared.b16 {%0,%1,%2,%3},[%4];"
                 : "=r"(r0),"=r"(r1),"=r"(r2),"=r"(r3) : "r"(a));
}
__device__ __forceinline__ void ldsm4t(uint32_t& r0,uint32_t& r1,uint32_t& r2,uint32_t& r3,uint32_t a){
    asm volatile("ldmatrix.sync.aligned.m8n8.x4.trans.shared.b16 {%0,%1,%2,%3},[%4];"
                 : "=r"(r0),"=r"(r1),"=r"(r2),"=r"(r3) : "r"(a));
}
__device__ __forceinline__ void mma16(float& c0,float& c1,float& c2,float& c3,
                                      uint32_t a0,uint32_t a1,uint32_t a2,uint32_t a3,
                                      uint32_t b0,uint32_t b1){
    asm("mma.sync.aligned.m16n8k16.row.col.f32.f16.f16.f32 "
        "{%0,%1,%2,%3},{%4,%5,%6,%7},{%8,%9},{%0,%1,%2,%3};"
        : "+f"(c0),"+f"(c1),"+f"(c2),"+f"(c3)
        : "r"(a0),"r"(a1),"r"(a2),"r"(a3),"r"(b0),"r"(b1));
}

// issue cp.async fill of one 64x64 fp32 tile; thread writes rows nb+8i
__device__ __forceinline__ void cp_fill(const float* __restrict__ g,
                                        float* __restrict__ stg, int tg){
#pragma unroll
    for (int i = 0; i < 8; i++){
        int f = tg + (i << 7);
        int n = f >> 4, c4 = (f & 15) << 2;
        cpa16(s2u(&stg[n*SF + c4]), &g[(n << 6) + c4]);
    }
    CP_COMMIT();
}

// staging fp32 -> elu+1 -> fp16, fused butterfly denominators (+opt norm regs).
// Each thread reads exactly the rows it cp.async'd (same-thread wait0 visibility).
__device__ __forceinline__ void cvt_denom(const float* __restrict__ stg,
                                          __half* __restrict__ dst, int tg, int lane,
                                          float n0f, float n1f, float n2f, float n3f,
                                          float* __restrict__ sI,
                                          bool donorm, float (&nrm)[4]){
    const int nb = tg >> 4, c4 = (tg & 15) << 2;
    float rp[8];
#pragma unroll
    for (int i = 0; i < 8; i++){
        const int n = nb + (i << 3);
        float4 v = *(const float4*)&stg[n*SF + c4];
        v.x = elu1(v.x); v.y = elu1(v.y); v.z = elu1(v.z); v.w = elu1(v.w);
        if (donorm){ nrm[0] += v.x; nrm[1] += v.y; nrm[2] += v.z; nrm[3] += v.w; }
        float t = v.x * n0f;
        t = fmaf(v.y, n1f, t); t = fmaf(v.z, n2f, t); t = fmaf(v.w, n3f, t);
        rp[i] = t;
        uint2 u;
        u.x = h2u(__floats2half2_rn(v.x, v.y));
        u.y = h2u(__floats2half2_rn(v.z, v.w));
        *(uint2*)&dst[n*SH + c4] = u;
    }
#pragma unroll
    for (int m = 1; m < 16; m <<= 1)
#pragma unroll
        for (int i = 0; i < 8; i++)
            rp[i] += __shfl_xor_sync(0xffffffffu, rp[i], m);
    if ((lane & 15) == 0)
#pragma unroll
        for (int i = 0; i < 8; i++)
            sI[nb + (i << 3)] = 1.f / fmaxf(rp[i], EPSV);
}

__global__ void init_tail(const float* __restrict__ pkv,
                          const float* __restrict__ pnorm,
                          float* __restrict__ dout){
    int i = blockIdx.x * 256 + threadIdx.x;
    if (i < KV_SIZE) dout[KV_OFF + i]   = pkv[i];
    if (i < 64*64)   dout[NORM_OFF + i] = pnorm[i];
}

__global__ void __launch_bounds__(256, 2) fw_kernel(
    const float* __restrict__ keys, const float* __restrict__ values,
    const float* __restrict__ queries, const float* __restrict__ outin,
    const float* __restrict__ pkv, const float* __restrict__ pnorm,
    const float* __restrict__ gates, float* __restrict__ dout)
{
    extern __shared__ __align__(16) char smraw[];
    __half* smh = (__half*)smraw;
    float*  smf = (float*)(smraw + F_BASE_BYTES);
    float* sN   = smf;
    float* sNrm = smf + 192;

    const int tid = threadIdx.x;
    const int g   = tid >> 7, tg = tid & 127;
    const int lane = tid & 31;
    const int wg  = (tid >> 5) & 3;
    const int gid = lane >> 2, tig = lane & 3;
    const int n0  = wg << 4;
    const int bh  = blockIdx.y;
    const size_t gOff = (size_t)bh * (8192*64);
    const int rowBase = blockIdx.x * 256;
    const int bid = 1 + g;

    __half* sKV = smh + H_KV;

    // ldmatrix lane geometry
    const int ar  = (((lane>>3)&1) << 3) + (lane & 7);
    const int ac  = (lane >> 4) << 3;
    const int ar2 = ((lane >> 4) << 3) + (lane & 7);
    const int ac2 = ((lane >> 3) & 1) << 3;
    const uint32_t bKV = s2u(&sKV[ar*SH + ac]);

    // ---- shared prologue: past_kv -> fp16, norm, zero sNrm ----
#pragma unroll
    for (int i = 0; i < 4; i++){
        int f = tid + (i << 8);
        int n = f >> 4, c4 = (f & 15) << 2;
        float4 v = *(const float4*)&pkv[(size_t)bh*4096 + (n << 6) + c4];
        uint2 u;
        u.x = h2u(__floats2half2_rn(v.x, v.y));
        u.y = h2u(__floats2half2_rn(v.z, v.w));
        *(uint2*)&sKV[n*SH + c4] = u;
    }
    if (tid < 64){ sN[tid] = pnorm[bh*64 + tid]; sNrm[tid] = 0.f; }

    const float et  = __expf(-gates[bh & 15]);
    const float gte = 1.f/(1.f+et), omg = et/(1.f+et);
    const int c4t = (tg & 15) << 2;

    if (g == 0){
        // ================= UPDATE PATH: k,v -> new_kv,new_norm =================
        __half* sK = smh + H_K;
        __half* sV = smh + H_V;
        float* stg = (float*)(smraw + STG0_BYTES);
        float* sI  = smf + 64;
        const uint32_t aK  = s2u(&sK[(n0 + ar)*SH + ac]);
        const uint32_t aK2 = s2u(&sK[ar2*SH + n0 + ac2]);
        const uint32_t bV  = s2u(&sV[ar*SH + ac]);

        cp_fill(keys + gOff + (size_t)rowBase*64, stg, tg);
        __syncthreads();          // KV + sN visible everywhere
        const float n0f = sN[c4t], n1f = sN[c4t+1], n2f = sN[c4t+2], n3f = sN[c4t+3];

        float acc[8][4];
#pragma unroll
        for (int a = 0; a < 8; a++){ acc[a][0]=0.f; acc[a][1]=0.f; acc[a][2]=0.f; acc[a][3]=0.f; }
        float nrm[4] = {0.f, 0.f, 0.f, 0.f};

        for (int ch = 0; ch < 4; ++ch){
            const int row0 = rowBase + (ch << 6);

            // A: consume staged k (fused denom+norm); refill with k(ch+1)
            CP_WAIT0();
            cvt_denom(stg, sK, tg, lane, n0f, n1f, n2f, n3f, sI, true, nrm);
            if (ch < 3) cp_fill(keys + gOff + (size_t)(row0+64)*64, stg, tg);
            barg(bid);

            // B: GEMM1 (values hoisted) + fused v-update into sV
            const float i1 = sI[n0+gid], i2 = sI[n0+gid+8];
            const size_t vr1 = gOff + (size_t)(row0+n0+gid)*64;
            const size_t vr2 = vr1 + 512;
            float2 va[8], vb[8];
#pragma unroll
            for (int idx = 0; idx < 8; idx++){
                const int cc = ((idx>>2)<<5) + ((idx&3)<<3) + (tig<<1);
                va[idx] = *(const float2*)&values[vr1 + cc];
                vb[idx] = *(const float2*)&values[vr2 + cc];
            }
#pragma unroll
            for (int pass = 0; pass < 2; pass++){
                float c[4][4];
#pragma unroll
                for (int nt = 0; nt < 4; nt++){ c[nt][0]=0.f; c[nt][1]=0.f; c[nt][2]=0.f; c[nt][3]=0.f; }
#pragma unroll
                for (int ks = 0; ks < 4; ks++){
                    const int k0 = ks << 4;
                    uint32_t a0,a1,a2,a3;
                    ldsm4(a0,a1,a2,a3, aK + (k0 << 1));
#pragma unroll
                    for (int ntp = 0; ntp < 2; ntp++){
                        uint32_t b0,b1,b2,b3;
                        ldsm4t(b0,b1,b2,b3, bKV + ((k0*SH + (pass<<5) + (ntp<<4)) << 1));
                        mma16(c[2*ntp][0],c[2*ntp][1],c[2*ntp][2],c[2*ntp][3],
                              a0,a1,a2,a3, b0,b1);
                        mma16(c[2*ntp+1][0],c[2*ntp+1][1],c[2*ntp+1][2],c[2*ntp+1][3],
                              a0,a1,a2,a3, b2,b3);
                    }
                }
#pragma unroll
                for (int nt = 0; nt < 4; nt++){
                    const int cc = (pass<<5) + (nt<<3) + (tig<<1);
                    const int idx = (pass<<2) + nt;
                    __half2 h1 = __floats2half2_rn(va[idx].x - c[nt][0]*i1,
                                                   va[idx].y - c[nt][1]*i1);
                    __half2 h2 = __floats2half2_rn(vb[idx].x - c[nt][2]*i2,
                                                   vb[idx].y - c[nt][3]*i2);
                    *(uint32_t*)&sV[(n0+gid)*SH + cc]   = h2u(h1);
                    *(uint32_t*)&sV[(n0+gid+8)*SH + cc] = h2u(h2);
                }
            }
            barg(bid);

            // C: GEMM2 acc += k^T v
#pragma unroll
            for (int ks = 0; ks < 4; ks++){
                const int k0 = ks << 4;
                uint32_t a0,a1,a2,a3;
                ldsm4t(a0,a1,a2,a3, aK2 + ((k0*SH) << 1));
#pragma unroll
                for (int ntp = 0; ntp < 4; ntp++){
                    uint32_t b0,b1,b2,b3;
                    ldsm4t(b0,b1,b2,b3, bV + ((k0*SH + (ntp<<4)) << 1));
                    mma16(acc[2*ntp][0],acc[2*ntp][1],acc[2*ntp][2],acc[2*ntp][3],
                          a0,a1,a2,a3, b0,b1);
                    mma16(acc[2*ntp+1][0],acc[2*ntp+1][1],acc[2*ntp+1][2],acc[2*ntp+1][3],
                          a0,a1,a2,a3, b2,b3);
                }
            }
            barg(bid);               // sK/sV reused next chunk
        }

        // ---- flush new_kv / new_norm ----
#pragma unroll
        for (int j = 0; j < 4; j++) atomicAdd(&sNrm[c4t + j], nrm[j]);
        float* kvout = dout + KV_OFF + bh * 4096;
#pragma unroll
        for (int j = 0; j < 8; j++){
            const int cc = (j<<3) + (tig<<1);
            float* r1 = &kvout[(n0+gid)*64 + cc];
            float* r2 = &kvout[(n0+gid+8)*64 + cc];
            atomicAdd(r1,   acc[j][0]); atomicAdd(r1+1, acc[j][1]);
            atomicAdd(r2,   acc[j][2]); atomicAdd(r2+1, acc[j][3]);
        }
        barg(bid);
        if (tg < 64) atomicAdd(&dout[NORM_OFF + bh*64 + tg], sNrm[tg]);
    } else {
        // ================= RETRIEVE PATH: q -> gated out ======================
        __half* sQ = smh + H_Q;
        float* stg = (float*)(smraw + STG1_BYTES);
        float* sI  = smf + 128;
        const uint32_t aQ = s2u(&sQ[(n0 + ar)*SH + ac]);

        cp_fill(queries + gOff + (size_t)rowBase*64, stg, tg);
        __syncthreads();          // KV + sN visible everywhere
        const float n0f = sN[c4t], n1f = sN[c4t+1], n2f = sN[c4t+2], n3f = sN[c4t+3];
        float nrmDummy[4] = {0.f, 0.f, 0.f, 0.f};

        for (int ch = 0; ch < 4; ++ch){
            const int row0 = rowBase + (ch << 6);

            // A: consume staged q (fused denom); refill with q(ch+1)
            CP_WAIT0();
            cvt_denom(stg, sQ, tg, lane, n0f, n1f, n2f, n3f, sI, false, nrmDummy);
            if (ch < 3) cp_fill(queries + gOff + (size_t)(row0+64)*64, stg, tg);
            barg(bid);

            // B: GEMM3 (out hoisted) + gated epilogue
            const float s1 = sI[n0+gid]*omg, s2 = sI[n0+gid+8]*omg;
            const size_t r1 = gOff + (size_t)(row0+n0+gid)*64;
            const size_t r2 = r1 + 512;
            float2 oa[8], ob[8];
#pragma unroll
            for (int idx = 0; idx < 8; idx++){
                const int cc = ((idx>>2)<<5) + ((idx&3)<<3) + (tig<<1);
                oa[idx] = *(const float2*)&outin[r1 + cc];
                ob[idx] = *(const float2*)&outin[r2 + cc];
            }
#pragma unroll
            for (int pass = 0; pass < 2; pass++){
                float c[4][4];
#pragma unroll
                for (int nt = 0; nt < 4; nt++){ c[nt][0]=0.f; c[nt][1]=0.f; c[nt][2]=0.f; c[nt][3]=0.f; }
#pragma unroll
                for (int ks = 0; ks < 4; ks++){
                    const int k0 = ks << 4;
                    uint32_t a0,a1,a2,a3;
                    ldsm4(a0,a1,a2,a3, aQ + (k0 << 1));
#pragma unroll
                    for (int ntp = 0; ntp < 2; ntp++){
                        uint32_t b0,b1,b2,b3;
                        ldsm4t(b0,b1,b2,b3, bKV + ((k0*SH + (pass<<5) + (ntp<<4)) << 1));
                        mma16(c[2*ntp][0],c[2*ntp][1],c[2*ntp][2],c[2*ntp][3],
                              a0,a1,a2,a3, b0,b1);
                        mma16(c[2*ntp+1][0],c[2*ntp+1][1],c[2*ntp+1][2],c[2*ntp+1][3],
                              a0,a1,a2,a3, b2,b3);
                    }
                }
#pragma unroll
                for (int nt = 0; nt < 4; nt++){
                    const int cc = (pass<<5) + (nt<<3) + (tig<<1);
                    const int idx = (pass<<2) + nt;
                    float2 o1 = oa[idx], o2 = ob[idx];
                    o1.x = o1.x*gte + c[nt][0]*s1; o1.y = o1.y*gte + c[nt][1]*s1;
                    o2.x = o2.x*gte + c[nt][2]*s2; o2.y = o2.y*gte + c[nt][3]*s2;
                    *(float2*)&dout[r1 + cc] = o1;
                    *(float2*)&dout[r2 + cc] = o2;
                }
            }
            barg(bid);               // sQ/sI reused next chunk
        }
    }
}

extern "C" void kernel_launch(void* const* d_in, const int* in_sizes, int n_in,
                              void* d_out, int out_size)
{
    const float* keys    = (const float*)d_in[0];
    const float* values  = (const float*)d_in[1];
    const float* queries = (const float*)d_in[2];
    const float* outin   = (const float*)d_in[3];
    const float* pkv     = (const float*)d_in[4];
    const float* pnorm   = (const float*)d_in[5];
    const float* gates   = (const float*)d_in[6];
    float* dout = (float*)d_out;

    cudaFuncSetAttribute(fw_kernel, cudaFuncAttributeMaxDynamicSharedMemorySize, SMEM_BYTES);

    init_tail<<<1024, 256>>>(pkv, pnorm, dout);
    fw_kernel<<<dim3(32, 64), 256, SMEM_BYTES>>>(keys, values, queries, outin,
                                                 pkv, pnorm, gates, dout);
}

// round 9
// speedup vs baseline: 3.5125x; 1.0726x over previous
#include <cuda_runtime.h>
#include <cuda_fp16.h>
#include <cstdint>

#define KV_OFF   (64*8192*64)
#define KV_SIZE  (64*64*64)
#define NORM_OFF (KV_OFF + KV_SIZE)
#define EPSV 1e-10f
#define SH 72                     // halves per fp16 tile row (144B)
#define SF 68                     // floats per fp32 staging row

// half-index offsets for fp16 tiles
#define H_KV 0                    // 64 x SH shared past_kv
#define H_K  4608
#define H_V  9216
#define H_Q  13824
// byte offsets for fp32 staging buffers (each 64*SF*4 = 17408B)
#define STGK_B 36864
#define STGV_B 54272
#define STGQ_B 71680
#define STGO_B 89088
#define F_BASE_BYTES 106496       // sN[64], sI0[64], sI1[64], sNrm[64]
#define SMEM_BYTES (F_BASE_BYTES + 1024)

__device__ __forceinline__ float elu1(float x){ return x > 0.f ? x + 1.f : __expf(x); }
__device__ __forceinline__ uint32_t s2u(const void* p){ return (uint32_t)__cvta_generic_to_shared(p); }
__device__ __forceinline__ void barg(int id){ asm volatile("bar.sync %0, 128;" :: "r"(id) : "memory"); }
__device__ __forceinline__ uint32_t h2u(__half2 h){ return *reinterpret_cast<uint32_t*>(&h); }
__device__ __forceinline__ void cpa16(uint32_t s, const void* g){
    asm volatile("cp.async.cg.shared.global [%0], [%1], 16;" :: "r"(s), "l"(g));
}
#define CP_COMMIT() asm volatile("cp.async.commit_group;")
#define CP_WAIT(n)  asm volatile("cp.async.wait_group %0;" :: "n"(n))

__device__ __forceinline__ void ldsm4(uint32_t& r0,uint32_t& r1,uint32_t& r2,uint32_t& r3,uint32_t a){
    asm volatile("ldmatrix.sync.aligned.m8n8.x4.shared.b16 {%0,%1,%2,%3},[%4];"
                 : "=r"(r0),"=r"(r1),"=r"(r2),"=r"(r3) : "r"(a));
}
__device__ __forceinline__ void ldsm4t(uint32_t& r0,uint32_t& r1,uint32_t& r2,uint32_t& r3,uint32_t a){
    asm volatile("ldmatrix.sync.aligned.m8n8.x4.trans.shared.b16 {%0,%1,%2,%3},[%4];"
                 : "=r"(r0),"=r"(r1),"=r"(r2),"=r"(r3) : "r"(a));
}
__device__ __forceinline__ void mma16(float& c0,float& c1,float& c2,float& c3,
                                      uint32_t a0,uint32_t a1,uint32_t a2,uint32_t a3,
                                      uint32_t b0,uint32_t b1){
    asm("mma.sync.aligned.m16n8k16.row.col.f32.f16.f16.f32 "
        "{%0,%1,%2,%3},{%4,%5,%6,%7},{%8,%9},{%0,%1,%2,%3};"
        : "+f"(c0),"+f"(c1),"+f"(c2),"+f"(c3)
        : "r"(a0),"r"(a1),"r"(a2),"r"(a3),"r"(b0),"r"(b1));
}

// issue cp.async fill of one 64x64 fp32 tile (thread owns rows nb+8i); commits a group
__device__ __forceinline__ void cp_fill(const float* __restrict__ g,
                                        float* __restrict__ stg, int tg){
#pragma unroll
    for (int i = 0; i < 8; i++){
        int f = tg + (i << 7);
        int n = f >> 4, c4 = (f & 15) << 2;
        cpa16(s2u(&stg[n*SF + c4]), &g[(n << 6) + c4]);
    }
    CP_COMMIT();
}

// staging fp32 -> elu+1 -> fp16, fused butterfly denominators (+opt norm regs).
// Each thread reads exactly the rows it cp.async'd (same-thread wait visibility).
__device__ __forceinline__ void cvt_denom(const float* __restrict__ stg,
                                          __half* __restrict__ dst, int tg, int lane,
                                          float n0f, float n1f, float n2f, float n3f,
                                          float* __restrict__ sI,
                                          bool donorm, float (&nrm)[4]){
    const int nb = tg >> 4, c4 = (tg & 15) << 2;
    float rp[8];
#pragma unroll
    for (int i = 0; i < 8; i++){
        const int n = nb + (i << 3);
        float4 v = *(const float4*)&stg[n*SF + c4];
        v.x = elu1(v.x); v.y = elu1(v.y); v.z = elu1(v.z); v.w = elu1(v.w);
        if (donorm){ nrm[0] += v.x; nrm[1] += v.y; nrm[2] += v.z; nrm[3] += v.w; }
        float t = v.x * n0f;
        t = fmaf(v.y, n1f, t); t = fmaf(v.z, n2f, t); t = fmaf(v.w, n3f, t);
        rp[i] = t;
        uint2 u;
        u.x = h2u(__floats2half2_rn(v.x, v.y));
        u.y = h2u(__floats2half2_rn(v.z, v.w));
        *(uint2*)&dst[n*SH + c4] = u;
    }
#pragma unroll
    for (int m = 1; m < 16; m <<= 1)
#pragma unroll
        for (int i = 0; i < 8; i++)
            rp[i] += __shfl_xor_sync(0xffffffffu, rp[i], m);
    if ((lane & 15) == 0)
#pragma unroll
        for (int i = 0; i < 8; i++)
            sI[nb + (i << 3)] = 1.f / fmaxf(rp[i], EPSV);
}

__global__ void init_tail(const float* __restrict__ pkv,
                          const float* __restrict__ pnorm,
                          float* __restrict__ dout){
    int i = blockIdx.x * 256 + threadIdx.x;
    if (i < KV_SIZE) dout[KV_OFF + i]   = pkv[i];
    if (i < 64*64)   dout[NORM_OFF + i] = pnorm[i];
}

__global__ void __launch_bounds__(256, 2) fw_kernel(
    const float* __restrict__ keys, const float* __restrict__ values,
    const float* __restrict__ queries, const float* __restrict__ outin,
    const float* __restrict__ pkv, const float* __restrict__ pnorm,
    const float* __restrict__ gates, float* __restrict__ dout)
{
    extern __shared__ __align__(16) char smraw[];
    __half* smh = (__half*)smraw;
    float*  smf = (float*)(smraw + F_BASE_BYTES);
    float* sN   = smf;
    float* sNrm = smf + 192;

    const int tid = threadIdx.x;
    const int g   = tid >> 7, tg = tid & 127;
    const int lane = tid & 31;
    const int wg  = (tid >> 5) & 3;
    const int gid = lane >> 2, tig = lane & 3;
    const int n0  = wg << 4;
    const int bh  = blockIdx.y;
    const size_t gOff = (size_t)bh * (8192*64);
    const int rowBase = blockIdx.x * 256;
    const int bid = 1 + g;

    __half* sKV = smh + H_KV;

    // ldmatrix lane geometry
    const int ar  = (((lane>>3)&1) << 3) + (lane & 7);
    const int ac  = (lane >> 4) << 3;
    const int ar2 = ((lane >> 4) << 3) + (lane & 7);
    const int ac2 = ((lane >> 3) & 1) << 3;
    const uint32_t bKV = s2u(&sKV[ar*SH + ac]);

    // ---- shared prologue: past_kv -> fp16, norm, zero sNrm ----
#pragma unroll
    for (int i = 0; i < 4; i++){
        int f = tid + (i << 8);
        int n = f >> 4, c4 = (f & 15) << 2;
        float4 v = *(const float4*)&pkv[(size_t)bh*4096 + (n << 6) + c4];
        uint2 u;
        u.x = h2u(__floats2half2_rn(v.x, v.y));
        u.y = h2u(__floats2half2_rn(v.z, v.w));
        *(uint2*)&sKV[n*SH + c4] = u;
    }
    if (tid < 64){ sN[tid] = pnorm[bh*64 + tid]; sNrm[tid] = 0.f; }

    const float et  = __expf(-gates[bh & 15]);
    const float gte = 1.f/(1.f+et), omg = et/(1.f+et);
    const int c4t = (tg & 15) << 2;

    if (g == 0){
        // ================= UPDATE PATH: k,v -> new_kv,new_norm =================
        __half* sK = smh + H_K;
        __half* sV = smh + H_V;
        float* stgK = (float*)(smraw + STGK_B);
        float* stgV = (float*)(smraw + STGV_B);
        float* sI  = smf + 64;
        const uint32_t aK  = s2u(&sK[(n0 + ar)*SH + ac]);
        const uint32_t aK2 = s2u(&sK[ar2*SH + n0 + ac2]);
        const uint32_t bV  = s2u(&sV[ar*SH + ac]);

        // prologue commits: [k0][v0]
        cp_fill(keys   + gOff + (size_t)rowBase*64, stgK, tg);
        cp_fill(values + gOff + (size_t)rowBase*64, stgV, tg);
        __syncthreads();          // KV + sN visible everywhere
        const float n0f = sN[c4t], n1f = sN[c4t+1], n2f = sN[c4t+2], n3f = sN[c4t+3];

        float acc[8][4];
#pragma unroll
        for (int a = 0; a < 8; a++){ acc[a][0]=0.f; acc[a][1]=0.f; acc[a][2]=0.f; acc[a][3]=0.f; }
        float nrm[4] = {0.f, 0.f, 0.f, 0.f};

        for (int ch = 0; ch < 4; ++ch){
            const int row0 = rowBase + (ch << 6);

            // -- phase A: k(ch) done (v(ch) still newest); cvt; prefetch k(ch+1);
            //    then drain v(ch) and barrier (publishes staged v to all threads)
            CP_WAIT(1);
            cvt_denom(stgK, sK, tg, lane, n0f, n1f, n2f, n3f, sI, true, nrm);
            if (ch < 3){
                cp_fill(keys + gOff + (size_t)(row0+64)*64, stgK, tg);
                CP_WAIT(1);        // queue [v(ch), k(ch+1)] -> v(ch) done
            } else {
                CP_WAIT(0);        // queue [v(3)] -> done
            }
            barg(bid);

            // -- phase B: GEMM1 + fused v-update (values from staged smem) --
            const float i1 = sI[n0+gid], i2 = sI[n0+gid+8];
#pragma unroll
            for (int pass = 0; pass < 2; pass++){
                float c[4][4];
#pragma unroll
                for (int nt = 0; nt < 4; nt++){ c[nt][0]=0.f; c[nt][1]=0.f; c[nt][2]=0.f; c[nt][3]=0.f; }
#pragma unroll
                for (int ks = 0; ks < 4; ks++){
                    const int k0 = ks << 4;
                    uint32_t a0,a1,a2,a3;
                    ldsm4(a0,a1,a2,a3, aK + (k0 << 1));
#pragma unroll
                    for (int ntp = 0; ntp < 2; ntp++){
                        uint32_t b0,b1,b2,b3;
                        ldsm4t(b0,b1,b2,b3, bKV + ((k0*SH + (pass<<5) + (ntp<<4)) << 1));
                        mma16(c[2*ntp][0],c[2*ntp][1],c[2*ntp][2],c[2*ntp][3],
                              a0,a1,a2,a3, b0,b1);
                        mma16(c[2*ntp+1][0],c[2*ntp+1][1],c[2*ntp+1][2],c[2*ntp+1][3],
                              a0,a1,a2,a3, b2,b3);
                    }
                }
#pragma unroll
                for (int nt = 0; nt < 4; nt++){
                    const int cc = (pass<<5) + (nt<<3) + (tig<<1);
                    const float2 v1 = *(const float2*)&stgV[(n0+gid)*SF + cc];
                    const float2 v2 = *(const float2*)&stgV[(n0+gid+8)*SF + cc];
                    __half2 h1 = __floats2half2_rn(v1.x - c[nt][0]*i1,
                                                   v1.y - c[nt][1]*i1);
                    __half2 h2 = __floats2half2_rn(v2.x - c[nt][2]*i2,
                                                   v2.y - c[nt][3]*i2);
                    *(uint32_t*)&sV[(n0+gid)*SH + cc]   = h2u(h1);
                    *(uint32_t*)&sV[(n0+gid+8)*SH + cc] = h2u(h2);
                }
            }
            barg(bid);             // sV ready; stgV fully consumed
            if (ch < 3)
                cp_fill(values + gOff + (size_t)(row0+64)*64, stgV, tg);

            // -- phase C: GEMM2 acc += k^T v --
#pragma unroll
            for (int ks = 0; ks < 4; ks++){
                const int k0 = ks << 4;
                uint32_t a0,a1,a2,a3;
                ldsm4t(a0,a1,a2,a3, aK2 + ((k0*SH) << 1));
#pragma unroll
                for (int ntp = 0; ntp < 4; ntp++){
                    uint32_t b0,b1,b2,b3;
                    ldsm4t(b0,b1,b2,b3, bV + ((k0*SH + (ntp<<4)) << 1));
                    mma16(acc[2*ntp][0],acc[2*ntp][1],acc[2*ntp][2],acc[2*ntp][3],
                          a0,a1,a2,a3, b0,b1);
                    mma16(acc[2*ntp+1][0],acc[2*ntp+1][1],acc[2*ntp+1][2],acc[2*ntp+1][3],
                          a0,a1,a2,a3, b2,b3);
                }
            }
            barg(bid);             // sK/sV reused next chunk
        }

        // ---- flush new_kv / new_norm ----
#pragma unroll
        for (int j = 0; j < 4; j++) atomicAdd(&sNrm[c4t + j], nrm[j]);
        float* kvout = dout + KV_OFF + bh * 4096;
#pragma unroll
        for (int j = 0; j < 8; j++){
            const int cc = (j<<3) + (tig<<1);
            float* r1 = &kvout[(n0+gid)*64 + cc];
            float* r2 = &kvout[(n0+gid+8)*64 + cc];
            atomicAdd(r1,   acc[j][0]); atomicAdd(r1+1, acc[j][1]);
            atomicAdd(r2,   acc[j][2]); atomicAdd(r2+1, acc[j][3]);
        }
        barg(bid);
        if (tg < 64) atomicAdd(&dout[NORM_OFF + bh*64 + tg], sNrm[tg]);
    } else {
        // ================= RETRIEVE PATH: q -> gated out ======================
        __half* sQ = smh + H_Q;
        float* stgQ = (float*)(smraw + STGQ_B);
        float* stgO = (float*)(smraw + STGO_B);
        float* sI  = smf + 128;
        const uint32_t aQ = s2u(&sQ[(n0 + ar)*SH + ac]);

        // prologue commits: [q0][o0]
        cp_fill(queries + gOff + (size_t)rowBase*64, stgQ, tg);
        cp_fill(outin   + gOff + (size_t)rowBase*64, stgO, tg);
        __syncthreads();          // KV + sN visible everywhere
        const float n0f = sN[c4t], n1f = sN[c4t+1], n2f = sN[c4t+2], n3f = sN[c4t+3];
        float nrmDummy[4] = {0.f, 0.f, 0.f, 0.f};

        for (int ch = 0; ch < 4; ++ch){
            const int row0 = rowBase + (ch << 6);

            // -- phase A: q(ch) done; cvt; prefetch q(ch+1); drain o(ch); barrier
            CP_WAIT(1);
            cvt_denom(stgQ, sQ, tg, lane, n0f, n1f, n2f, n3f, sI, false, nrmDummy);
            if (ch < 3){
                cp_fill(queries + gOff + (size_t)(row0+64)*64, stgQ, tg);
                CP_WAIT(1);        // queue [o(ch), q(ch+1)] -> o(ch) done
            } else {
                CP_WAIT(0);
            }
            barg(bid);

            // -- phase B: GEMM3 + gated epilogue (out from staged smem) --
            const float s1 = sI[n0+gid]*omg, s2 = sI[n0+gid+8]*omg;
            const size_t r1 = gOff + (size_t)(row0+n0+gid)*64;
            const size_t r2 = r1 + 512;
#pragma unroll
            for (int pass = 0; pass < 2; pass++){
                float c[4][4];
#pragma unroll
                for (int nt = 0; nt < 4; nt++){ c[nt][0]=0.f; c[nt][1]=0.f; c[nt][2]=0.f; c[nt][3]=0.f; }
#pragma unroll
                for (int ks = 0; ks < 4; ks++){
                    const int k0 = ks << 4;
                    uint32_t a0,a1,a2,a3;
                    ldsm4(a0,a1,a2,a3, aQ + (k0 << 1));
#pragma unroll
                    for (int ntp = 0; ntp < 2; ntp++){
                        uint32_t b0,b1,b2,b3;
                        ldsm4t(b0,b1,b2,b3, bKV + ((k0*SH + (pass<<5) + (ntp<<4)) << 1));
                        mma16(c[2*ntp][0],c[2*ntp][1],c[2*ntp][2],c[2*ntp][3],
                              a0,a1,a2,a3, b0,b1);
                        mma16(c[2*ntp+1][0],c[2*ntp+1][1],c[2*ntp+1][2],c[2*ntp+1][3],
                              a0,a1,a2,a3, b2,b3);
                    }
                }
#pragma unroll
                for (int nt = 0; nt < 4; nt++){
                    const int cc = (pass<<5) + (nt<<3) + (tig<<1);
                    float2 o1 = *(const float2*)&stgO[(n0+gid)*SF + cc];
                    float2 o2 = *(const float2*)&stgO[(n0+gid+8)*SF + cc];
                    o1.x = o1.x*gte + c[nt][0]*s1; o1.y = o1.y*gte + c[nt][1]*s1;
                    o2.x = o2.x*gte + c[nt][2]*s2; o2.y = o2.y*gte + c[nt][3]*s2;
                    *(float2*)&dout[r1 + cc] = o1;
                    *(float2*)&dout[r2 + cc] = o2;
                }
            }
            barg(bid);             // sQ/sI/stgO reused next chunk
            if (ch < 3)
                cp_fill(outin + gOff + (size_t)(row0+64)*64, stgO, tg);
        }
    }
}

extern "C" void kernel_launch(void* const* d_in, const int* in_sizes, int n_in,
                              void* d_out, int out_size)
{
    const float* keys    = (const float*)d_in[0];
    const float* values  = (const float*)d_in[1];
    const float* queries = (const float*)d_in[2];
    const float* outin   = (const float*)d_in[3];
    const float* pkv     = (const float*)d_in[4];
    const float* pnorm   = (const float*)d_in[5];
    const float* gates   = (const float*)d_in[6];
    float* dout = (float*)d_out;

    cudaFuncSetAttribute(fw_kernel, cudaFuncAttributeMaxDynamicSharedMemorySize, SMEM_BYTES);

    init_tail<<<1024, 256>>>(pkv, pnorm, dout);
    fw_kernel<<<dim3(32, 64), 256, SMEM_BYTES>>>(keys, values, queries, outin,
                                                 pkv, pnorm, gates, dout);
}

// round 10
// speedup vs baseline: 3.6361x; 1.0352x over previous
#include <cuda_runtime.h>
#include <cuda_fp16.h>
#include <cstdint>

#define KV_OFF   (64*8192*64)
#define KV_SIZE  (64*64*64)
#define NORM_OFF (KV_OFF + KV_SIZE)
#define EPSV 1e-10f
#define SH 72                     // halves per fp16 tile row (144B)
#define SF 68                     // floats per fp32 staging row

// half-index offsets for fp16 tiles
#define H_KV 0                    // 64 x SH shared past_kv
#define H_K  4608
#define H_V  9216
#define H_Q  13824
// byte offsets for fp32 staging buffers (each 64*SF*4 = 17408B)
#define STGK_B 36864
#define STGV_B 54272
#define STGQ_B 71680
#define STGO_B 89088
#define F_BASE_BYTES 106496       // sN[64], sIu[64], sIr[64], sNrm[64]
#define SMEM_BYTES (F_BASE_BYTES + 1024)

__device__ __forceinline__ float elu1(float x){ return x > 0.f ? x + 1.f : __expf(x); }
__device__ __forceinline__ uint32_t s2u(const void* p){ return (uint32_t)__cvta_generic_to_shared(p); }
__device__ __forceinline__ void bar256(){ asm volatile("bar.sync 1, 256;" ::: "memory"); }
__device__ __forceinline__ void bar128(){ asm volatile("bar.sync 2, 128;" ::: "memory"); }
__device__ __forceinline__ uint32_t h2u(__half2 h){ return *reinterpret_cast<uint32_t*>(&h); }
__device__ __forceinline__ void cpa16(uint32_t s, const void* g){
    asm volatile("cp.async.cg.shared.global [%0], [%1], 16;" :: "r"(s), "l"(g));
}
#define CP_COMMIT() asm volatile("cp.async.commit_group;")
#define CP_WAIT(n)  asm volatile("cp.async.wait_group %0;" :: "n"(n))

__device__ __forceinline__ void ldsm4(uint32_t& r0,uint32_t& r1,uint32_t& r2,uint32_t& r3,uint32_t a){
    asm volatile("ldmatrix.sync.aligned.m8n8.x4.shared.b16 {%0,%1,%2,%3},[%4];"
                 : "=r"(r0),"=r"(r1),"=r"(r2),"=r"(r3) : "r"(a));
}
__device__ __forceinline__ void ldsm4t(uint32_t& r0,uint32_t& r1,uint32_t& r2,uint32_t& r3,uint32_t a){
    asm volatile("ldmatrix.sync.aligned.m8n8.x4.trans.shared.b16 {%0,%1,%2,%3},[%4];"
                 : "=r"(r0),"=r"(r1),"=r"(r2),"=r"(r3) : "r"(a));
}
__device__ __forceinline__ void mma16(float& c0,float& c1,float& c2,float& c3,
                                      uint32_t a0,uint32_t a1,uint32_t a2,uint32_t a3,
                                      uint32_t b0,uint32_t b1){
    asm("mma.sync.aligned.m16n8k16.row.col.f32.f16.f16.f32 "
        "{%0,%1,%2,%3},{%4,%5,%6,%7},{%8,%9},{%0,%1,%2,%3};"
        : "+f"(c0),"+f"(c1),"+f"(c2),"+f"(c3)
        : "r"(a0),"r"(a1),"r"(a2),"r"(a3),"r"(b0),"r"(b1));
}

// ---- 128-thread staging (retrieve group): 8 x 16B per thread ----
__device__ __forceinline__ void cp_fill128(const float* __restrict__ g,
                                           float* __restrict__ stg, int tg){
#pragma unroll
    for (int i = 0; i < 8; i++){
        int f = tg + (i << 7);
        int n = f >> 4, c4 = (f & 15) << 2;
        cpa16(s2u(&stg[n*SF + c4]), &g[(n << 6) + c4]);
    }
    CP_COMMIT();
}
// ---- 256-thread staging (update group): 4 x 16B per thread ----
__device__ __forceinline__ void cp_fill256(const float* __restrict__ g,
                                           float* __restrict__ stg, int tg2){
#pragma unroll
    for (int i = 0; i < 4; i++){
        int f = tg2 + (i << 8);
        int n = f >> 4, c4 = (f & 15) << 2;
        cpa16(s2u(&stg[n*SF + c4]), &g[(n << 6) + c4]);
    }
    CP_COMMIT();
}

// fp32 staging -> elu+1 -> fp16, fused butterfly denominators (+opt nrm regs).
// 128-thread version: 8 rows/thread (rows nb+8i, matching cp_fill128).
__device__ __forceinline__ void cvt_denom128(const float* __restrict__ stg,
                                             __half* __restrict__ dst, int tg, int lane,
                                             float n0f, float n1f, float n2f, float n3f,
                                             float* __restrict__ sI){
    const int nb = tg >> 4, c4 = (tg & 15) << 2;
    float rp[8];
#pragma unroll
    for (int i = 0; i < 8; i++){
        const int n = nb + (i << 3);
        float4 v = *(const float4*)&stg[n*SF + c4];
        v.x = elu1(v.x); v.y = elu1(v.y); v.z = elu1(v.z); v.w = elu1(v.w);
        float t = v.x * n0f;
        t = fmaf(v.y, n1f, t); t = fmaf(v.z, n2f, t); t = fmaf(v.w, n3f, t);
        rp[i] = t;
        uint2 u;
        u.x = h2u(__floats2half2_rn(v.x, v.y));
        u.y = h2u(__floats2half2_rn(v.z, v.w));
        *(uint2*)&dst[n*SH + c4] = u;
    }
#pragma unroll
    for (int m = 1; m < 16; m <<= 1)
#pragma unroll
        for (int i = 0; i < 8; i++)
            rp[i] += __shfl_xor_sync(0xffffffffu, rp[i], m);
    if ((lane & 15) == 0)
#pragma unroll
        for (int i = 0; i < 8; i++)
            sI[nb + (i << 3)] = 1.f / fmaxf(rp[i], EPSV);
}
// 256-thread version: 4 rows/thread (rows (tg2>>4)+16i, matching cp_fill256);
// accumulates new_norm column partials.
__device__ __forceinline__ void cvt_denom256(const float* __restrict__ stg,
                                             __half* __restrict__ dst, int tg2, int lane,
                                             float n0f, float n1f, float n2f, float n3f,
                                             float* __restrict__ sI, float (&nrm)[4]){
    const int nb = tg2 >> 4, c4 = (tg2 & 15) << 2;
    float rp[4];
#pragma unroll
    for (int i = 0; i < 4; i++){
        const int n = nb + (i << 4);
        float4 v = *(const float4*)&stg[n*SF + c4];
        v.x = elu1(v.x); v.y = elu1(v.y); v.z = elu1(v.z); v.w = elu1(v.w);
        nrm[0] += v.x; nrm[1] += v.y; nrm[2] += v.z; nrm[3] += v.w;
        float t = v.x * n0f;
        t = fmaf(v.y, n1f, t); t = fmaf(v.z, n2f, t); t = fmaf(v.w, n3f, t);
        rp[i] = t;
        uint2 u;
        u.x = h2u(__floats2half2_rn(v.x, v.y));
        u.y = h2u(__floats2half2_rn(v.z, v.w));
        *(uint2*)&dst[n*SH + c4] = u;
    }
#pragma unroll
    for (int m = 1; m < 16; m <<= 1)
#pragma unroll
        for (int i = 0; i < 4; i++)
            rp[i] += __shfl_xor_sync(0xffffffffu, rp[i], m);
    if ((lane & 15) == 0)
#pragma unroll
        for (int i = 0; i < 4; i++)
            sI[nb + (i << 4)] = 1.f / fmaxf(rp[i], EPSV);
}

__global__ void init_tail(const float* __restrict__ pkv,
                          const float* __restrict__ pnorm,
                          float* __restrict__ dout){
    int i = blockIdx.x * 256 + threadIdx.x;
    if (i < KV_SIZE) dout[KV_OFF + i]   = pkv[i];
    if (i < 64*64)   dout[NORM_OFF + i] = pnorm[i];
}

__global__ void __launch_bounds__(384, 2) fw_kernel(
    const float* __restrict__ keys, const float* __restrict__ values,
    const float* __restrict__ queries, const float* __restrict__ outin,
    const float* __restrict__ pkv, const float* __restrict__ pnorm,
    const float* __restrict__ gates, float* __restrict__ dout)
{
    extern __shared__ __align__(16) char smraw[];
    __half* smh = (__half*)smraw;
    float*  smf = (float*)(smraw + F_BASE_BYTES);
    float* sN   = smf;
    float* sNrm = smf + 192;

    const int tid = threadIdx.x;
    const int lane = tid & 31;
    const int gid = lane >> 2, tig = lane & 3;
    const int bh  = blockIdx.y;
    const size_t gOff = (size_t)bh * (8192*64);
    const int rowBase = blockIdx.x * 256;

    __half* sKV = smh + H_KV;

    // ldmatrix lane geometry
    const int ar  = (((lane>>3)&1) << 3) + (lane & 7);
    const int ac  = (lane >> 4) << 3;
    const int ar2 = ((lane >> 4) << 3) + (lane & 7);
    const int ac2 = ((lane >> 3) & 1) << 3;
    const uint32_t bKV = s2u(&sKV[ar*SH + ac]);

    // ---- shared prologue: past_kv -> fp16, norm, zero sNrm ----
#pragma unroll
    for (int i = 0; i < 3; i++){
        int f = tid + i * 384;
        if (f < 1024){
            int n = f >> 4, c4 = (f & 15) << 2;
            float4 v = *(const float4*)&pkv[(size_t)bh*4096 + (n << 6) + c4];
            uint2 u;
            u.x = h2u(__floats2half2_rn(v.x, v.y));
            u.y = h2u(__floats2half2_rn(v.z, v.w));
            *(uint2*)&sKV[n*SH + c4] = u;
        }
    }
    if (tid < 64){ sN[tid] = pnorm[bh*64 + tid]; sNrm[tid] = 0.f; }

    const float et  = __expf(-gates[bh & 15]);
    const float gte = 1.f/(1.f+et), omg = et/(1.f+et);

    if (tid < 256){
        // ========== UPDATE GROUP (8 warps): k,v -> new_kv,new_norm ==========
        const int tg2 = tid;
        const int w   = tid >> 5;            // 0..7
        const int m0  = (w & 3) << 4;        // 16-row base
        const int coh = (w >> 2) << 5;       // 32-col half base
        __half* sK = smh + H_K;
        __half* sV = smh + H_V;
        float* stgK = (float*)(smraw + STGK_B);
        float* stgV = (float*)(smraw + STGV_B);
        float* sI  = smf + 64;
        const uint32_t aK  = s2u(&sK[(m0 + ar)*SH + ac]);
        const uint32_t aK2 = s2u(&sK[ar2*SH + m0 + ac2]);
        const uint32_t bV  = s2u(&sV[ar*SH + coh + ac]);
        const uint32_t bKVu = s2u(&sKV[ar*SH + coh + ac]);

        cp_fill256(keys   + gOff + (size_t)rowBase*64, stgK, tg2);
        cp_fill256(values + gOff + (size_t)rowBase*64, stgV, tg2);
        __syncthreads();
        const int c4t = (tg2 & 15) << 2;
        const float n0f = sN[c4t], n1f = sN[c4t+1], n2f = sN[c4t+2], n3f = sN[c4t+3];

        float acc[4][4];
#pragma unroll
        for (int a = 0; a < 4; a++){ acc[a][0]=0.f; acc[a][1]=0.f; acc[a][2]=0.f; acc[a][3]=0.f; }
        float nrm[4] = {0.f, 0.f, 0.f, 0.f};

        for (int ch = 0; ch < 4; ++ch){
            const int row0 = rowBase + (ch << 6);

            // A: k(ch) ready; cvt+denom; prefetch k(ch+1); drain v(ch); barrier
            CP_WAIT(1);
            cvt_denom256(stgK, sK, tg2, lane, n0f, n1f, n2f, n3f, sI, nrm);
            if (ch < 3){
                cp_fill256(keys + gOff + (size_t)(row0+64)*64, stgK, tg2);
                CP_WAIT(1);
            } else {
                CP_WAIT(0);
            }
            bar256();

            // B: GEMM1 quadrant (16 rows x 32 cols) + fused v-update
            {
                const float i1 = sI[m0+gid], i2 = sI[m0+gid+8];
                float c[4][4];
#pragma unroll
                for (int nt = 0; nt < 4; nt++){ c[nt][0]=0.f; c[nt][1]=0.f; c[nt][2]=0.f; c[nt][3]=0.f; }
#pragma unroll
                for (int ks = 0; ks < 4; ks++){
                    const int k0 = ks << 4;
                    uint32_t a0,a1,a2,a3;
                    ldsm4(a0,a1,a2,a3, aK + (k0 << 1));
#pragma unroll
                    for (int ntp = 0; ntp < 2; ntp++){
                        uint32_t b0,b1,b2,b3;
                        ldsm4t(b0,b1,b2,b3, bKVu + ((k0*SH + (ntp<<4)) << 1));
                        mma16(c[2*ntp][0],c[2*ntp][1],c[2*ntp][2],c[2*ntp][3],
                              a0,a1,a2,a3, b0,b1);
                        mma16(c[2*ntp+1][0],c[2*ntp+1][1],c[2*ntp+1][2],c[2*ntp+1][3],
                              a0,a1,a2,a3, b2,b3);
                    }
                }
#pragma unroll
                for (int nt = 0; nt < 4; nt++){
                    const int cc = coh + (nt<<3) + (tig<<1);
                    const float2 v1 = *(const float2*)&stgV[(m0+gid)*SF + cc];
                    const float2 v2 = *(const float2*)&stgV[(m0+gid+8)*SF + cc];
                    __half2 h1 = __floats2half2_rn(v1.x - c[nt][0]*i1,
                                                   v1.y - c[nt][1]*i1);
                    __half2 h2 = __floats2half2_rn(v2.x - c[nt][2]*i2,
                                                   v2.y - c[nt][3]*i2);
                    *(uint32_t*)&sV[(m0+gid)*SH + cc]   = h2u(h1);
                    *(uint32_t*)&sV[(m0+gid+8)*SH + cc] = h2u(h2);
                }
            }
            bar256();
            if (ch < 3)
                cp_fill256(values + gOff + (size_t)(row0+64)*64, stgV, tg2);

            // C: GEMM2 quadrant acc += k^T v (16 d x 32 e)
#pragma unroll
            for (int ks = 0; ks < 4; ks++){
                const int k0 = ks << 4;
                uint32_t a0,a1,a2,a3;
                ldsm4t(a0,a1,a2,a3, aK2 + ((k0*SH) << 1));
#pragma unroll
                for (int ntp = 0; ntp < 2; ntp++){
                    uint32_t b0,b1,b2,b3;
                    ldsm4t(b0,b1,b2,b3, bV + ((k0*SH + (ntp<<4)) << 1));
                    mma16(acc[2*ntp][0],acc[2*ntp][1],acc[2*ntp][2],acc[2*ntp][3],
                          a0,a1,a2,a3, b0,b1);
                    mma16(acc[2*ntp+1][0],acc[2*ntp+1][1],acc[2*ntp+1][2],acc[2*ntp+1][3],
                          a0,a1,a2,a3, b2,b3);
                }
            }
            bar256();
        }

        // ---- flush new_kv / new_norm ----
#pragma unroll
        for (int j = 0; j < 4; j++) atomicAdd(&sNrm[c4t + j], nrm[j]);
        float* kvout = dout + KV_OFF + bh * 4096;
#pragma unroll
        for (int j = 0; j < 4; j++){
            const int cc = coh + (j<<3) + (tig<<1);
            float* r1 = &kvout[(m0+gid)*64 + cc];
            float* r2 = &kvout[(m0+gid+8)*64 + cc];
            atomicAdd(r1,   acc[j][0]); atomicAdd(r1+1, acc[j][1]);
            atomicAdd(r2,   acc[j][2]); atomicAdd(r2+1, acc[j][3]);
        }
        bar256();
        if (tg2 < 64) atomicAdd(&dout[NORM_OFF + bh*64 + tg2], sNrm[tg2]);
    } else {
        // ========== RETRIEVE GROUP (4 warps): q -> gated out ==========
        const int tg = tid & 127;
        const int n0 = ((tid >> 5) - 8) << 4;     // warp row base 0..48
        __half* sQ = smh + H_Q;
        float* stgQ = (float*)(smraw + STGQ_B);
        float* stgO = (float*)(smraw + STGO_B);
        float* sI  = smf + 128;
        const uint32_t aQ = s2u(&sQ[(n0 + ar)*SH + ac]);

        cp_fill128(queries + gOff + (size_t)rowBase*64, stgQ, tg);
        cp_fill128(outin   + gOff + (size_t)rowBase*64, stgO, tg);
        __syncthreads();
        const int c4t = (tg & 15) << 2;
        const float n0f = sN[c4t], n1f = sN[c4t+1], n2f = sN[c4t+2], n3f = sN[c4t+3];

        for (int ch = 0; ch < 4; ++ch){
            const int row0 = rowBase + (ch << 6);

            // A: q(ch) ready; cvt+denom; prefetch q(ch+1); drain o(ch); barrier
            CP_WAIT(1);
            cvt_denom128(stgQ, sQ, tg, lane, n0f, n1f, n2f, n3f, sI);
            if (ch < 3){
                cp_fill128(queries + gOff + (size_t)(row0+64)*64, stgQ, tg);
                CP_WAIT(1);
            } else {
                CP_WAIT(0);
            }
            bar128();

            // B: GEMM3 (two 32-col passes) + gated epilogue from staged out
            const float s1 = sI[n0+gid]*omg, s2 = sI[n0+gid+8]*omg;
            const size_t r1 = gOff + (size_t)(row0+n0+gid)*64;
            const size_t r2 = r1 + 512;
#pragma unroll
            for (int pass = 0; pass < 2; pass++){
                float c[4][4];
#pragma unroll
                for (int nt = 0; nt < 4; nt++){ c[nt][0]=0.f; c[nt][1]=0.f; c[nt][2]=0.f; c[nt][3]=0.f; }
#pragma unroll
                for (int ks = 0; ks < 4; ks++){
                    const int k0 = ks << 4;
                    uint32_t a0,a1,a2,a3;
                    ldsm4(a0,a1,a2,a3, aQ + (k0 << 1));
#pragma unroll
                    for (int ntp = 0; ntp < 2; ntp++){
                        uint32_t b0,b1,b2,b3;
                        ldsm4t(b0,b1,b2,b3, bKV + ((k0*SH + (pass<<5) + (ntp<<4)) << 1));
                        mma16(c[2*ntp][0],c[2*ntp][1],c[2*ntp][2],c[2*ntp][3],
                              a0,a1,a2,a3, b0,b1);
                        mma16(c[2*ntp+1][0],c[2*ntp+1][1],c[2*ntp+1][2],c[2*ntp+1][3],
                              a0,a1,a2,a3, b2,b3);
                    }
                }
#pragma unroll
                for (int nt = 0; nt < 4; nt++){
                    const int cc = (pass<<5) + (nt<<3) + (tig<<1);
                    float2 o1 = *(const float2*)&stgO[(n0+gid)*SF + cc];
                    float2 o2 = *(const float2*)&stgO[(n0+gid+8)*SF + cc];
                    o1.x = o1.x*gte + c[nt][0]*s1; o1.y = o1.y*gte + c[nt][1]*s1;
                    o2.x = o2.x*gte + c[nt][2]*s2; o2.y = o2.y*gte + c[nt][3]*s2;
                    *(float2*)&dout[r1 + cc] = o1;
                    *(float2*)&dout[r2 + cc] = o2;
                }
            }
            bar128();
            if (ch < 3)
                cp_fill128(outin + gOff + (size_t)(row0+64)*64, stgO, tg);
        }
    }
}

extern "C" void kernel_launch(void* const* d_in, const int* in_sizes, int n_in,
                              void* d_out, int out_size)
{
    const float* keys    = (const float*)d_in[0];
    const float* values  = (const float*)d_in[1];
    const float* queries = (const float*)d_in[2];
    const float* outin   = (const float*)d_in[3];
    const float* pkv     = (const float*)d_in[4];
    const float* pnorm   = (const float*)d_in[5];
    const float* gates   = (const float*)d_in[6];
    float* dout = (float*)d_out;

    cudaFuncSetAttribute(fw_kernel, cudaFuncAttributeMaxDynamicSharedMemorySize, SMEM_BYTES);

    init_tail<<<1024, 256>>>(pkv, pnorm, dout);
    fw_kernel<<<dim3(32, 64), 384, SMEM_BYTES>>>(keys, values, queries, outin,
                                                 pkv, pnorm, gates, dout);
}